// round 1
// baseline (speedup 1.0000x reference)
#include <cuda_runtime.h>
#include <math.h>

#define Bsz 32
#define Nn  100
#define Ee  9900
#define Hh  256
#define FIN 200
#define BE  (Bsz*Ee)    // 316800
#define BNr (Bsz*Nn)    // 3200
#define NPART 495       // 316800 / 495 = 640 rows per partial

// ---------------- scratch (static device globals; no allocation) ------------
__device__ float g_h1[BNr*Hh];
__device__ float g_na[BNr*Hh];
__device__ float g_nb[BNr*Hh];
__device__ float g_as[BNr*Hh];
__device__ float g_ar[BNr*Hh];
__device__ float g_xskip[BE*Hh];
__device__ float g_pre[BE*Hh];
__device__ float g_y4[BE*Hh];
__device__ int   g_send[Ee];
__device__ int   g_recv[Ee];
__device__ float g_part[NPART*2*Hh];
__device__ float g_fcW[Hh*2];
__device__ float g_fcB[2];

__device__ __forceinline__ float elu_f(float x) { return x > 0.f ? x : expm1f(x); }

// ---------------- edge index extraction from one-hot matrices ---------------
__global__ void build_idx_k(const float* __restrict__ rr, const float* __restrict__ rs) {
    int e = blockIdx.x * blockDim.x + threadIdx.x;
    if (e >= Ee) return;
    int r = 0, s = 0;
    for (int n = 0; n < Nn; n++) {
        if (rr[e*Nn + n] > 0.5f) r = n;
        if (rs[e*Nn + n] > 0.5f) s = n;
    }
    g_recv[e] = r;
    g_send[e] = s;
}

// ---------------- generic 64x64 tiled GEMM, N(out)=256 always ---------------
// AMODE 0: A is a plain [M,K] matrix (lda given), arbitrary K
// AMODE 1: A[row,k] = ELU(As[srow,k] + Ar[rrow,k] + bias1[k])          (K=256)
// AMODE 2: A[row,k] = ELU(Pre[row,k] + As[srow,k] + Ar[rrow,k] + b1[k]) (K=256)
template<int AMODE>
__global__ __launch_bounds__(256)
void gemm_k(const float* __restrict__ A, int lda, int K,
            const float* __restrict__ W,        // [K,256] row-major
            const float* __restrict__ bias,     // [256] or null
            int do_elu,
            const float* __restrict__ As_, const float* __restrict__ Ar_,
            const float* __restrict__ Pre_, const float* __restrict__ bias1,
            float* __restrict__ C, int M)
{
    __shared__ float sA[16][65];
    __shared__ float sB[16][64];
    __shared__ int ssend[64], srecv[64];

    const int row0 = blockIdx.x * 64;
    const int col0 = blockIdx.y * 64;
    const int tid  = threadIdx.x;
    const int ty   = tid >> 4, tx = tid & 15;

    if (AMODE > 0) {
        if (tid < 64) {
            int row = row0 + tid;
            int b = row / Ee;
            int e = row - b * Ee;
            ssend[tid] = (b * Nn + g_send[e]) * Hh;
            srecv[tid] = (b * Nn + g_recv[e]) * Hh;
        }
        __syncthreads();
    }

    float acc[4][4] = {};

    for (int kt = 0; kt < K; kt += 16) {
        #pragma unroll
        for (int i = 0; i < 4; i++) {
            int idx = tid + i * 256;
            int m = idx >> 4, k = idx & 15;
            int kk = kt + k;
            float v;
            if (AMODE == 0) {
                v = (kk < K) ? A[(size_t)(row0 + m) * lda + kk] : 0.f;
            } else {
                float t = As_[ssend[m] + kk] + Ar_[srecv[m] + kk] + bias1[kk];
                if (AMODE == 2) t += Pre_[(size_t)(row0 + m) * Hh + kk];
                v = elu_f(t);
            }
            sA[k][m] = v;
        }
        #pragma unroll
        for (int i = 0; i < 4; i++) {
            int idx = tid + i * 256;
            int k = idx >> 6, n = idx & 63;
            int kk = kt + k;
            sB[k][n] = (kk < K) ? W[(size_t)kk * 256 + col0 + n] : 0.f;
        }
        __syncthreads();

        #pragma unroll
        for (int k = 0; k < 16; k++) {
            float a[4], b[4];
            #pragma unroll
            for (int i = 0; i < 4; i++) a[i] = sA[k][ty*4 + i];
            #pragma unroll
            for (int j = 0; j < 4; j++) b[j] = sB[k][tx*4 + j];
            #pragma unroll
            for (int i = 0; i < 4; i++)
                #pragma unroll
                for (int j = 0; j < 4; j++)
                    acc[i][j] += a[i] * b[j];
        }
        __syncthreads();
    }

    #pragma unroll
    for (int i = 0; i < 4; i++) {
        int m = row0 + ty*4 + i;
        #pragma unroll
        for (int j = 0; j < 4; j++) {
            int n = col0 + tx*4 + j;
            float v = acc[i][j];
            if (bias) v += bias[n];
            if (do_elu) v = elu_f(v);
            C[(size_t)m * 256 + n] = v;
        }
    }
}

// ---------------- edge2node: contiguous 99-edge segment mean ----------------
__global__ void edge2node_k(const float* __restrict__ x, float* __restrict__ out) {
    int nodeRow = blockIdx.x;          // 0..3199
    int h = threadIdx.x;               // 0..255
    int b = nodeRow / Nn, n = nodeRow - b * Nn;
    const float* base = x + (size_t)(b * Ee + n * 99) * Hh + h;
    float s = 0.f;
    #pragma unroll 3
    for (int r = 0; r < 99; r++) s += base[(size_t)r * Hh];
    out[(size_t)nodeRow * Hh + h] = s * (1.0f / 9900.0f);
}

// ---------------- BN statistics: deterministic two-stage --------------------
__global__ void bn_part_k(const float* __restrict__ y) {
    int p = blockIdx.x;        // 0..NPART-1
    int ch = threadIdx.x;      // 0..255
    const int rows = BE / NPART;   // 640
    const float* base = y + (size_t)p * rows * Hh + ch;
    float s = 0.f, q = 0.f;
    for (int r = 0; r < rows; r++) {
        float v = base[(size_t)r * Hh];
        s += v;
        q += v * v;
    }
    g_part[p * 512 + ch]       = s;
    g_part[p * 512 + 256 + ch] = q;
}

__global__ void bn_fin_k(const float* __restrict__ gamma, const float* __restrict__ beta,
                         const float* __restrict__ W, const float* __restrict__ fb) {
    int ch = threadIdx.x;
    double s = 0.0, q = 0.0;
    for (int p = 0; p < NPART; p++) {
        s += (double)g_part[p * 512 + ch];
        q += (double)g_part[p * 512 + 256 + ch];
    }
    double m = s / (double)BE;
    double v = q / (double)BE - m * m;
    float sc = (float)(rsqrt(v + 1e-5) * (double)gamma[ch]);
    float sh = beta[ch] - (float)m * sc;
    float w0 = W[ch*2 + 0], w1 = W[ch*2 + 1];
    g_fcW[ch*2 + 0] = sc * w0;
    g_fcW[ch*2 + 1] = sc * w1;
    __shared__ float r0s[256], r1s[256];
    r0s[ch] = sh * w0;
    r1s[ch] = sh * w1;
    __syncthreads();
    for (int st = 128; st > 0; st >>= 1) {
        if (ch < st) { r0s[ch] += r0s[ch + st]; r1s[ch] += r1s[ch + st]; }
        __syncthreads();
    }
    if (ch == 0) { g_fcB[0] = r0s[0] + fb[0]; g_fcB[1] = r1s[0] + fb[1]; }
}

// ---------------- final fc (folded BN): warp per row ------------------------
__global__ void fc_k(const float* __restrict__ y, float* __restrict__ out) {
    int gwarp = (blockIdx.x * blockDim.x + threadIdx.x) >> 5;
    int lane  = threadIdx.x & 31;
    if (gwarp >= BE) return;
    const float* row = y + (size_t)gwarp * Hh;
    float a0 = 0.f, a1 = 0.f;
    #pragma unroll
    for (int i = lane; i < Hh; i += 32) {
        float v = row[i];
        a0 += v * g_fcW[i*2 + 0];
        a1 += v * g_fcW[i*2 + 1];
    }
    #pragma unroll
    for (int o = 16; o > 0; o >>= 1) {
        a0 += __shfl_down_sync(0xffffffffu, a0, o);
        a1 += __shfl_down_sync(0xffffffffu, a1, o);
    }
    if (lane == 0) {
        out[(size_t)gwarp * 2 + 0] = a0 + g_fcB[0];
        out[(size_t)gwarp * 2 + 1] = a1 + g_fcB[1];
    }
}

// ---------------------------------------------------------------------------
extern "C" void kernel_launch(void* const* d_in, const int* in_sizes, int n_in,
                              void* d_out, int out_size) {
    const float* inputs  = (const float*)d_in[0];
    const float* rel_rec = (const float*)d_in[1];
    const float* rel_snd = (const float*)d_in[2];
    const float* m1W1 = (const float*)d_in[3];  const float* m1b1 = (const float*)d_in[4];
    const float* m1W2 = (const float*)d_in[5];  const float* m1b2 = (const float*)d_in[6];
    const float* m2W1 = (const float*)d_in[7];  const float* m2b1 = (const float*)d_in[8];
    const float* m2W2 = (const float*)d_in[9];  const float* m2b2 = (const float*)d_in[10];
    const float* m3W1 = (const float*)d_in[11]; const float* m3b1 = (const float*)d_in[12];
    const float* m3W2 = (const float*)d_in[13]; const float* m3b2 = (const float*)d_in[14];
    const float* m4W1 = (const float*)d_in[15]; const float* m4b1 = (const float*)d_in[16];
    const float* m4W2 = (const float*)d_in[17]; const float* m4b2 = (const float*)d_in[18];
    const float* gmma = (const float*)d_in[19]; const float* beta = (const float*)d_in[20];
    const float* fcW  = (const float*)d_in[21]; const float* fcb  = (const float*)d_in[22];
    float* out = (float*)d_out;

    float *h1, *na, *nb, *as_, *ar_, *xskip, *pre, *y4;
    cudaGetSymbolAddress((void**)&h1, g_h1);
    cudaGetSymbolAddress((void**)&na, g_na);
    cudaGetSymbolAddress((void**)&nb, g_nb);
    cudaGetSymbolAddress((void**)&as_, g_as);
    cudaGetSymbolAddress((void**)&ar_, g_ar);
    cudaGetSymbolAddress((void**)&xskip, g_xskip);
    cudaGetSymbolAddress((void**)&pre, g_pre);
    cudaGetSymbolAddress((void**)&y4, g_y4);

    dim3 gN(BNr / 64, 4);     // node-level GEMMs (3200 rows)
    dim3 gE(BE / 64, 4);      // edge-level GEMMs (316800 rows)

    // edge index tables
    build_idx_k<<<(Ee + 127) / 128, 128>>>(rel_rec, rel_snd);

    // mlp1 (node level): [3200,200] -> 256 -> 256, ELU both
    gemm_k<0><<<gN, 256>>>(inputs, FIN, FIN, m1W1, m1b1, 1, nullptr, nullptr, nullptr, nullptr, na, BNr);
    gemm_k<0><<<gN, 256>>>(na, Hh, Hh, m1W2, m1b2, 1, nullptr, nullptr, nullptr, nullptr, h1, BNr);

    // node projections for mlp2 layer1 (concat split)
    gemm_k<0><<<gN, 256>>>(h1, Hh, Hh, m2W1,           nullptr, 0, nullptr, nullptr, nullptr, nullptr, as_, BNr);
    gemm_k<0><<<gN, 256>>>(h1, Hh, Hh, m2W1 + 256*256, nullptr, 0, nullptr, nullptr, nullptr, nullptr, ar_, BNr);

    // big edge GEMM #1: x_skip = ELU( ELU(as[s]+ar[r]+b1) @ W2 + b2 )
    gemm_k<1><<<gE, 256>>>(nullptr, Hh, Hh, m2W2, m2b2, 1, as_, ar_, nullptr, m2b1, xskip, BE);

    // edge2node (contiguous segment mean over 99 edges per receiver)
    edge2node_k<<<BNr, 256>>>(xskip, na);

    // mlp3 (node level)
    gemm_k<0><<<gN, 256>>>(na, Hh, Hh, m3W1, m3b1, 1, nullptr, nullptr, nullptr, nullptr, nb, BNr);
    gemm_k<0><<<gN, 256>>>(nb, Hh, Hh, m3W2, m3b2, 1, nullptr, nullptr, nullptr, nullptr, h1, BNr);

    // node projections for mlp4 layer1 (send2 / recv2 parts of the [768,256] W)
    gemm_k<0><<<gN, 256>>>(h1, Hh, Hh, m4W1,           nullptr, 0, nullptr, nullptr, nullptr, nullptr, as_, BNr);
    gemm_k<0><<<gN, 256>>>(h1, Hh, Hh, m4W1 + 256*256, nullptr, 0, nullptr, nullptr, nullptr, nullptr, ar_, BNr);

    // big edge GEMM #2: pre = x_skip @ W4_1[512:768]
    gemm_k<0><<<gE, 256>>>(xskip, Hh, Hh, m4W1 + 512*256, nullptr, 0, nullptr, nullptr, nullptr, nullptr, pre, BE);

    // big edge GEMM #3: y4 = ELU( ELU(pre + as[s]+ar[r]+b1) @ W4_2 + b2 )
    gemm_k<2><<<gE, 256>>>(nullptr, Hh, Hh, m4W2, m4b2, 1, as_, ar_, pre, m4b1, y4, BE);

    // BN stats (deterministic), fold into fc, final fc
    bn_part_k<<<NPART, 256>>>(y4);
    bn_fin_k<<<1, 256>>>(gmma, beta, fcW, fcb);
    fc_k<<<(BE * 32 + 255) / 256, 256>>>(y4, out);
}

// round 3
// speedup vs baseline: 1.8954x; 1.8954x over previous
#include <cuda_runtime.h>
#include <cuda_bf16.h>
#include <math.h>
#include <cstdint>

#define Bsz 32
#define Nn  100
#define Ee  9900
#define Hh  256
#define FIN 200
#define BE  (Bsz*Ee)    // 316800
#define BNr (Bsz*Nn)    // 3200
#define NPART 495

// ---------------- scratch (static device globals) ---------------------------
__device__ float g_h1[BNr*Hh];
__device__ float g_na[BNr*Hh];
__device__ float g_nb[BNr*Hh];
__device__ float g_as[BNr*Hh];
__device__ float g_ar[BNr*Hh];
__device__ float g_xskip[(size_t)BE*Hh];
__device__ float g_pre[(size_t)BE*Hh];
__device__ float g_y4[(size_t)BE*Hh];
__device__ int   g_send[Ee];
__device__ int   g_recv[Ee];
__device__ float g_part[NPART*2*Hh];
__device__ float g_fcW[Hh*2];
__device__ float g_fcB[2];
// transposed + bf16-split weight images: [n][k] layout, 3 mats
__device__ __nv_bfloat16 g_WtHi[3][65536];
__device__ __nv_bfloat16 g_WtLo[3][65536];

__device__ __forceinline__ float elu_f(float x) { return x > 0.f ? x : expm1f(x); }

__device__ __forceinline__ uint32_t smem_u32(const void* p) {
    uint32_t a;
    asm("{ .reg .u64 t; cvta.to.shared.u64 t, %1; cvt.u32.u64 %0, t; }" : "=r"(a) : "l"(p));
    return a;
}
__device__ __forceinline__ uint32_t pack_bf2(__nv_bfloat16 a, __nv_bfloat16 b) {
    __nv_bfloat162 h2; h2.x = a; h2.y = b;
    return *reinterpret_cast<uint32_t*>(&h2);
}

#define LDSM4(r, addr) \
    asm volatile("ldmatrix.sync.aligned.m8n8.x4.shared.b16 {%0,%1,%2,%3}, [%4];" \
        : "=r"((r)[0]), "=r"((r)[1]), "=r"((r)[2]), "=r"((r)[3]) : "r"(addr))

#define MMA16816(d, a, b0, b1) \
    asm volatile("mma.sync.aligned.m16n8k16.row.col.f32.bf16.bf16.f32 " \
        "{%0,%1,%2,%3},{%4,%5,%6,%7},{%8,%9},{%0,%1,%2,%3};" \
        : "+f"((d)[0]), "+f"((d)[1]), "+f"((d)[2]), "+f"((d)[3]) \
        : "r"((a)[0]), "r"((a)[1]), "r"((a)[2]), "r"((a)[3]), "r"(b0), "r"(b1))

// ---------------- edge index extraction -------------------------------------
__global__ void build_idx_k(const float* __restrict__ rr, const float* __restrict__ rs) {
    int e = blockIdx.x * blockDim.x + threadIdx.x;
    if (e >= Ee) return;
    int r = 0, s = 0;
    for (int n = 0; n < Nn; n++) {
        if (rr[e*Nn + n] > 0.5f) r = n;
        if (rs[e*Nn + n] > 0.5f) s = n;
    }
    g_recv[e] = r;
    g_send[e] = s;
}

// ---------------- weight prep: transpose [k][n]->[n][k] + bf16 split --------
__global__ void prep_wt_k(const float* __restrict__ W,
                          __nv_bfloat16* __restrict__ Hi, __nv_bfloat16* __restrict__ Lo) {
    __shared__ float t[32][33];
    int k0 = blockIdx.x * 32, n0 = blockIdx.y * 32;
    int tx = threadIdx.x, ty = threadIdx.y;
    t[ty][tx] = W[(k0 + ty) * 256 + n0 + tx];
    __syncthreads();
    float v = t[tx][ty];            // element (k = k0+tx, n = n0+ty)
    __nv_bfloat16 h = __float2bfloat16(v);
    __nv_bfloat16 l = __float2bfloat16(v - __bfloat162float(h));
    Hi[(n0 + ty) * 256 + k0 + tx] = h;
    Lo[(n0 + ty) * 256 + k0 + tx] = l;
}

// ---------------- big tensor-core GEMM via mma.sync bf16 split --------------
// CTA: 128 rows x 128 cols, K=256 in 8 chunks of 32.
// AMODE 0: A = Amat                     (plain)
// AMODE 1: A = ELU(As[s]+Ar[r]+b1)
// AMODE 2: A = ELU(Amat + As[s]+Ar[r]+b1)
#define AHI 0
#define ALO 10240
#define BHI 20480
#define BLO 30720
#define SMTOT 40960

template<int AMODE>
__global__ __launch_bounds__(256, 1)
void gemm_tc(const float* __restrict__ Amat,
             const __nv_bfloat16* __restrict__ WtHi, const __nv_bfloat16* __restrict__ WtLo,
             const float* __restrict__ As_, const float* __restrict__ Ar_,
             const float* __restrict__ b1,
             const float* __restrict__ bias, int do_elu,
             float* __restrict__ C)
{
    __shared__ char sm[SMTOT];
    __shared__ int sidx[128], ridx[128];

    const int tid  = threadIdx.x;
    const int lane = tid & 31, w = tid >> 5;
    const int row0 = blockIdx.x * 128;
    const int nbase = blockIdx.y * 128;
    const uint32_t sbase = smem_u32(sm);

    if (AMODE != 0 && tid < 128) {
        int row = row0 + tid;
        int b = row / Ee, e = row - b * Ee;
        sidx[tid] = (b * Nn + g_send[e]) * Hh;
        ridx[tid] = (b * Nn + g_recv[e]) * Hh;
    }
    __syncthreads();

    // per-warp tile origin
    const int m0w = (w & 3) * 32;
    const int n0w = (w >> 2) * 64;
    // ldmatrix lane address components
    const int laneA_row = (lane & 7) + ((lane >> 3) & 1) * 8;
    const int laneA_k   = ((lane >> 4) & 1) * 8;
    const int laneB_row = (lane & 7) + ((lane >> 4) & 1) * 8;
    const int laneB_k   = ((lane >> 3) & 1) * 8;

    uint32_t aBase[2], bBase[4];
    #pragma unroll
    for (int i = 0; i < 2; i++)
        aBase[i] = sbase + (uint32_t)((m0w + i*16 + laneA_row) * 80 + laneA_k * 2);
    #pragma unroll
    for (int jp = 0; jp < 4; jp++)
        bBase[jp] = sbase + (uint32_t)(BHI + (n0w + jp*16 + laneB_row) * 80 + laneB_k * 2);

    float acc[16][4];
    #pragma unroll
    for (int t = 0; t < 16; t++) { acc[t][0]=0.f; acc[t][1]=0.f; acc[t][2]=0.f; acc[t][3]=0.f; }

    // prefetch state
    const int rowA = tid >> 1;
    const int kh   = (tid & 1) * 16;
    const int rowB = tid >> 1;
    const int halfB = tid & 1;

    float4 pS[4], pR[4], pP[4];
    uint4  pBh[2], pBl[2];

    #define LOAD_CHUNK(c) do { \
        int k0 = (c) * 32 + kh; \
        if (AMODE == 0 || AMODE == 2) { \
            _Pragma("unroll") \
            for (int i = 0; i < 4; i++) \
                pP[i] = *(const float4*)(Amat + (size_t)(row0 + rowA) * 256 + k0 + 4*i); \
        } \
        if (AMODE != 0) { \
            _Pragma("unroll") \
            for (int i = 0; i < 4; i++) { \
                pS[i] = *(const float4*)(As_ + sidx[rowA] + k0 + 4*i); \
                pR[i] = *(const float4*)(Ar_ + ridx[rowA] + k0 + 4*i); \
            } \
        } \
        const uint4* sh = (const uint4*)(WtHi + (size_t)(nbase + rowB) * 256 + (c) * 32 + halfB * 16); \
        const uint4* sl = (const uint4*)(WtLo + (size_t)(nbase + rowB) * 256 + (c) * 32 + halfB * 16); \
        pBh[0] = sh[0]; pBh[1] = sh[1]; \
        pBl[0] = sl[0]; pBl[1] = sl[1]; \
    } while (0)

    LOAD_CHUNK(0);

    #pragma unroll 1
    for (int c = 0; c < 8; ++c) {
        __syncthreads();   // previous chunk's mma done: smem reusable

        // ---- consume prefetched A: combine + ELU + bf16 split, store to smem
        {
            int k0 = c * 32 + kh;
            float v[16];
            #pragma unroll
            for (int i = 0; i < 4; i++) {
                float4 t;
                if (AMODE == 0) {
                    t = pP[i];
                } else {
                    float4 b4 = *(const float4*)(b1 + k0 + 4*i);
                    t.x = pS[i].x + pR[i].x + b4.x;
                    t.y = pS[i].y + pR[i].y + b4.y;
                    t.z = pS[i].z + pR[i].z + b4.z;
                    t.w = pS[i].w + pR[i].w + b4.w;
                    if (AMODE == 2) { t.x += pP[i].x; t.y += pP[i].y; t.z += pP[i].z; t.w += pP[i].w; }
                    t.x = elu_f(t.x); t.y = elu_f(t.y); t.z = elu_f(t.z); t.w = elu_f(t.w);
                }
                v[4*i+0] = t.x; v[4*i+1] = t.y; v[4*i+2] = t.z; v[4*i+3] = t.w;
            }
            uint32_t hp[8], lp[8];
            #pragma unroll
            for (int q = 0; q < 8; q++) {
                float f0 = v[2*q], f1 = v[2*q+1];
                __nv_bfloat16 h0 = __float2bfloat16(f0), h1 = __float2bfloat16(f1);
                __nv_bfloat16 l0 = __float2bfloat16(f0 - __bfloat162float(h0));
                __nv_bfloat16 l1 = __float2bfloat16(f1 - __bfloat162float(h1));
                hp[q] = pack_bf2(h0, h1);
                lp[q] = pack_bf2(l0, l1);
            }
            uint4* dh = (uint4*)(sm + AHI + rowA * 80 + kh * 2);
            uint4* dl = (uint4*)(sm + ALO + rowA * 80 + kh * 2);
            dh[0] = make_uint4(hp[0], hp[1], hp[2], hp[3]);
            dh[1] = make_uint4(hp[4], hp[5], hp[6], hp[7]);
            dl[0] = make_uint4(lp[0], lp[1], lp[2], lp[3]);
            dl[1] = make_uint4(lp[4], lp[5], lp[6], lp[7]);
            // B copy
            uint4* bh = (uint4*)(sm + BHI + rowB * 80 + halfB * 32);
            uint4* bl = (uint4*)(sm + BLO + rowB * 80 + halfB * 32);
            bh[0] = pBh[0]; bh[1] = pBh[1];
            bl[0] = pBl[0]; bl[1] = pBl[1];
        }
        __syncthreads();

        if (c < 7) LOAD_CHUNK(c + 1);   // loads fly during mma below

        // ---- mma over this 32-k chunk
        #pragma unroll
        for (int ks = 0; ks < 2; ++ks) {
            uint32_t ah[2][4], al[2][4], bh[8][2], bl[8][2];
            #pragma unroll
            for (int i = 0; i < 2; i++) {
                LDSM4(ah[i], aBase[i] + AHI + ks * 32);
                LDSM4(al[i], aBase[i] + ALO + ks * 32);
            }
            #pragma unroll
            for (int jp = 0; jp < 4; jp++) {
                uint32_t t4[4];
                LDSM4(t4, bBase[jp] + ks * 32);
                bh[2*jp][0] = t4[0]; bh[2*jp][1] = t4[1];
                bh[2*jp+1][0] = t4[2]; bh[2*jp+1][1] = t4[3];
                LDSM4(t4, bBase[jp] + 10240 + ks * 32);
                bl[2*jp][0] = t4[0]; bl[2*jp][1] = t4[1];
                bl[2*jp+1][0] = t4[2]; bl[2*jp+1][1] = t4[3];
            }
            #pragma unroll
            for (int i = 0; i < 2; i++) {
                #pragma unroll
                for (int j = 0; j < 8; j++) {
                    MMA16816(acc[i*8+j], ah[i], bh[j][0], bh[j][1]);
                    MMA16816(acc[i*8+j], ah[i], bl[j][0], bl[j][1]);
                    MMA16816(acc[i*8+j], al[i], bh[j][0], bh[j][1]);
                }
            }
        }
    }

    // ---- epilogue: bias + ELU, fp32 stores
    const int g  = lane >> 2;
    const int tg = lane & 3;
    #pragma unroll
    for (int i = 0; i < 2; i++) {
        #pragma unroll
        for (int j = 0; j < 8; j++) {
            int colg = nbase + n0w + j*8 + tg*2;
            float b0v = 0.f, b1v = 0.f;
            if (bias) { b0v = __ldg(bias + colg); b1v = __ldg(bias + colg + 1); }
            float* q = acc[i*8+j];
            int rlo = row0 + m0w + i*16 + g;
            int rhi = rlo + 8;
            float2 o0, o1;
            o0.x = q[0] + b0v; o0.y = q[1] + b1v;
            o1.x = q[2] + b0v; o1.y = q[3] + b1v;
            if (do_elu) {
                o0.x = elu_f(o0.x); o0.y = elu_f(o0.y);
                o1.x = elu_f(o1.x); o1.y = elu_f(o1.y);
            }
            *(float2*)(C + (size_t)rlo * 256 + colg) = o0;
            *(float2*)(C + (size_t)rhi * 256 + colg) = o1;
        }
    }
}

// ---------------- small node-level SIMT GEMM (M=3200) -----------------------
__global__ __launch_bounds__(256)
void gemm_node(const float* __restrict__ A, int lda, int K,
               const float* __restrict__ W, const float* __restrict__ bias,
               int do_elu, float* __restrict__ C)
{
    __shared__ float sA[16][65];
    __shared__ float sB[16][64];
    const int row0 = blockIdx.x * 64;
    const int col0 = blockIdx.y * 64;
    const int tid  = threadIdx.x;
    const int ty   = tid >> 4, tx = tid & 15;
    float acc[4][4] = {};
    for (int kt = 0; kt < K; kt += 16) {
        #pragma unroll
        for (int i = 0; i < 4; i++) {
            int idx = tid + i * 256;
            int m = idx >> 4, k = idx & 15;
            int kk = kt + k;
            sA[k][m] = (kk < K) ? A[(size_t)(row0 + m) * lda + kk] : 0.f;
        }
        #pragma unroll
        for (int i = 0; i < 4; i++) {
            int idx = tid + i * 256;
            int k = idx >> 6, n = idx & 63;
            int kk = kt + k;
            sB[k][n] = (kk < K) ? W[(size_t)kk * 256 + col0 + n] : 0.f;
        }
        __syncthreads();
        #pragma unroll
        for (int k = 0; k < 16; k++) {
            float a[4], b[4];
            #pragma unroll
            for (int i = 0; i < 4; i++) a[i] = sA[k][ty*4 + i];
            #pragma unroll
            for (int j = 0; j < 4; j++) b[j] = sB[k][tx*4 + j];
            #pragma unroll
            for (int i = 0; i < 4; i++)
                #pragma unroll
                for (int j = 0; j < 4; j++)
                    acc[i][j] += a[i] * b[j];
        }
        __syncthreads();
    }
    #pragma unroll
    for (int i = 0; i < 4; i++) {
        int m = row0 + ty*4 + i;
        #pragma unroll
        for (int j = 0; j < 4; j++) {
            int n = col0 + tx*4 + j;
            float v = acc[i][j];
            if (bias) v += bias[n];
            if (do_elu) v = elu_f(v);
            C[(size_t)m * 256 + n] = v;
        }
    }
}

// ---------------- edge2node: contiguous 99-edge segment mean ----------------
__global__ void edge2node_k(const float* __restrict__ x, float* __restrict__ out) {
    int nodeRow = blockIdx.x;
    int h = threadIdx.x;
    int b = nodeRow / Nn, n = nodeRow - b * Nn;
    const float* base = x + (size_t)(b * Ee + n * 99) * Hh + h;
    float s = 0.f;
    #pragma unroll 3
    for (int r = 0; r < 99; r++) s += base[(size_t)r * Hh];
    out[(size_t)nodeRow * Hh + h] = s * (1.0f / 9900.0f);
}

// ---------------- BN statistics: deterministic two-stage --------------------
__global__ void bn_part_k(const float* __restrict__ y) {
    int p = blockIdx.x;
    int ch = threadIdx.x;
    const int rows = BE / NPART;
    const float* base = y + (size_t)p * rows * Hh + ch;
    float s = 0.f, q = 0.f;
    for (int r = 0; r < rows; r++) {
        float v = base[(size_t)r * Hh];
        s += v;
        q += v * v;
    }
    g_part[p * 512 + ch]       = s;
    g_part[p * 512 + 256 + ch] = q;
}

__global__ void bn_fin_k(const float* __restrict__ gamma, const float* __restrict__ beta,
                         const float* __restrict__ W, const float* __restrict__ fb) {
    int ch = threadIdx.x;
    double s = 0.0, q = 0.0;
    for (int p = 0; p < NPART; p++) {
        s += (double)g_part[p * 512 + ch];
        q += (double)g_part[p * 512 + 256 + ch];
    }
    double m = s / (double)BE;
    double v = q / (double)BE - m * m;
    float sc = (float)(rsqrt(v + 1e-5) * (double)gamma[ch]);
    float sh = beta[ch] - (float)m * sc;
    float w0 = W[ch*2 + 0], w1 = W[ch*2 + 1];
    g_fcW[ch*2 + 0] = sc * w0;
    g_fcW[ch*2 + 1] = sc * w1;
    __shared__ float r0s[256], r1s[256];
    r0s[ch] = sh * w0;
    r1s[ch] = sh * w1;
    __syncthreads();
    for (int st = 128; st > 0; st >>= 1) {
        if (ch < st) { r0s[ch] += r0s[ch + st]; r1s[ch] += r1s[ch + st]; }
        __syncthreads();
    }
    if (ch == 0) { g_fcB[0] = r0s[0] + fb[0]; g_fcB[1] = r1s[0] + fb[1]; }
}

// ---------------- final fc (folded BN): warp per row ------------------------
__global__ void fc_k(const float* __restrict__ y, float* __restrict__ out) {
    int gwarp = (blockIdx.x * blockDim.x + threadIdx.x) >> 5;
    int lane  = threadIdx.x & 31;
    if (gwarp >= BE) return;
    const float* row = y + (size_t)gwarp * Hh;
    float a0 = 0.f, a1 = 0.f;
    #pragma unroll
    for (int i = lane; i < Hh; i += 32) {
        float v = row[i];
        a0 += v * g_fcW[i*2 + 0];
        a1 += v * g_fcW[i*2 + 1];
    }
    #pragma unroll
    for (int o = 16; o > 0; o >>= 1) {
        a0 += __shfl_down_sync(0xffffffffu, a0, o);
        a1 += __shfl_down_sync(0xffffffffu, a1, o);
    }
    if (lane == 0) {
        out[(size_t)gwarp * 2 + 0] = a0 + g_fcB[0];
        out[(size_t)gwarp * 2 + 1] = a1 + g_fcB[1];
    }
}

// ---------------------------------------------------------------------------
extern "C" void kernel_launch(void* const* d_in, const int* in_sizes, int n_in,
                              void* d_out, int out_size) {
    const float* inputs  = (const float*)d_in[0];
    const float* rel_rec = (const float*)d_in[1];
    const float* rel_snd = (const float*)d_in[2];
    const float* m1W1 = (const float*)d_in[3];  const float* m1b1 = (const float*)d_in[4];
    const float* m1W2 = (const float*)d_in[5];  const float* m1b2 = (const float*)d_in[6];
    const float* m2W1 = (const float*)d_in[7];  const float* m2b1 = (const float*)d_in[8];
    const float* m2W2 = (const float*)d_in[9];  const float* m2b2 = (const float*)d_in[10];
    const float* m3W1 = (const float*)d_in[11]; const float* m3b1 = (const float*)d_in[12];
    const float* m3W2 = (const float*)d_in[13]; const float* m3b2 = (const float*)d_in[14];
    const float* m4W1 = (const float*)d_in[15]; const float* m4b1 = (const float*)d_in[16];
    const float* m4W2 = (const float*)d_in[17]; const float* m4b2 = (const float*)d_in[18];
    const float* gmma = (const float*)d_in[19]; const float* beta = (const float*)d_in[20];
    const float* fcW  = (const float*)d_in[21]; const float* fcb  = (const float*)d_in[22];
    float* out = (float*)d_out;

    float *h1, *na, *nb, *as_, *ar_, *xskip, *pre, *y4;
    __nv_bfloat16 *wth, *wtl;
    cudaGetSymbolAddress((void**)&h1, g_h1);
    cudaGetSymbolAddress((void**)&na, g_na);
    cudaGetSymbolAddress((void**)&nb, g_nb);
    cudaGetSymbolAddress((void**)&as_, g_as);
    cudaGetSymbolAddress((void**)&ar_, g_ar);
    cudaGetSymbolAddress((void**)&xskip, g_xskip);
    cudaGetSymbolAddress((void**)&pre, g_pre);
    cudaGetSymbolAddress((void**)&y4, g_y4);
    cudaGetSymbolAddress((void**)&wth, g_WtHi);
    cudaGetSymbolAddress((void**)&wtl, g_WtLo);

    dim3 gN(BNr / 64, 4);
    dim3 gE(BE / 128, 2);
    dim3 tb(32, 32);
    dim3 tg(8, 8);

    // edge index tables + weight prep (transpose + bf16 split)
    build_idx_k<<<(Ee + 127) / 128, 128>>>(rel_rec, rel_snd);
    prep_wt_k<<<tg, tb>>>(m2W2,             wth + 0 * 65536, wtl + 0 * 65536);
    prep_wt_k<<<tg, tb>>>(m4W1 + 512 * 256, wth + 1 * 65536, wtl + 1 * 65536);
    prep_wt_k<<<tg, tb>>>(m4W2,             wth + 2 * 65536, wtl + 2 * 65536);

    // mlp1 (node level)
    gemm_node<<<gN, 256>>>(inputs, FIN, FIN, m1W1, m1b1, 1, na);
    gemm_node<<<gN, 256>>>(na, Hh, Hh, m1W2, m1b2, 1, h1);

    // node projections for mlp2 layer1 (concat split)
    gemm_node<<<gN, 256>>>(h1, Hh, Hh, m2W1,           nullptr, 0, as_);
    gemm_node<<<gN, 256>>>(h1, Hh, Hh, m2W1 + 256*256, nullptr, 0, ar_);

    // big GEMM #1 (tensor): xskip = ELU(ELU(as[s]+ar[r]+b1) @ W2 + b2)
    gemm_tc<1><<<gE, 256>>>(nullptr, wth + 0 * 65536, wtl + 0 * 65536,
                            as_, ar_, m2b1, m2b2, 1, xskip);

    // edge2node + mlp3 (node level)
    edge2node_k<<<BNr, 256>>>(xskip, na);
    gemm_node<<<gN, 256>>>(na, Hh, Hh, m3W1, m3b1, 1, nb);
    gemm_node<<<gN, 256>>>(nb, Hh, Hh, m3W2, m3b2, 1, h1);

    // node projections for mlp4 layer1
    gemm_node<<<gN, 256>>>(h1, Hh, Hh, m4W1,           nullptr, 0, as_);
    gemm_node<<<gN, 256>>>(h1, Hh, Hh, m4W1 + 256*256, nullptr, 0, ar_);

    // big GEMM #2 (tensor): pre = xskip @ W4_1[512:768]
    gemm_tc<0><<<gE, 256>>>(xskip, wth + 1 * 65536, wtl + 1 * 65536,
                            nullptr, nullptr, nullptr, nullptr, 0, pre);

    // big GEMM #3 (tensor): y4 = ELU(ELU(pre + as[s]+ar[r]+b1) @ W4_2 + b2)
    gemm_tc<2><<<gE, 256>>>(pre, wth + 2 * 65536, wtl + 2 * 65536,
                            as_, ar_, m4b1, m4b2, 1, y4);

    // BN stats (deterministic), fold into fc, final fc
    bn_part_k<<<NPART, 256>>>(y4);
    bn_fin_k<<<1, 256>>>(gmma, beta, fcW, fcb);
    fc_k<<<(BE * 32 + 255) / 256, 256>>>(y4, out);
}

// round 4
// speedup vs baseline: 1.9930x; 1.0515x over previous
#include <cuda_runtime.h>
#include <cuda_bf16.h>
#include <math.h>
#include <cstdint>

#define Bsz 32
#define Nn  100
#define Ee  9900
#define Hh  256
#define FIN 200
#define BE  (Bsz*Ee)    // 316800
#define BNr (Bsz*Nn)    // 3200
#define NCTA (BE/128)   // 2475

// ---------------- scratch (static device globals) ---------------------------
__device__ float g_h1[BNr*Hh];
__device__ float g_na[BNr*Hh];
__device__ float g_nb[BNr*Hh];
__device__ float g_as[BNr*Hh];
__device__ float g_ar[BNr*Hh];
__device__ float g_xskip[(size_t)BE*Hh];
__device__ float g_pre[(size_t)BE*Hh];
__device__ float g_y4[(size_t)BE*Hh];
__device__ int   g_send[Ee];
__device__ int   g_recv[Ee];
__device__ float g_p3[(size_t)NCTA*256*2];   // per-CTA BN partials (sum, sumsq)
__device__ float g_fcW[Hh*2];
__device__ float g_fcB[2];
// transposed + bf16-split weight images: [n][k] layout, 3 mats
__device__ __nv_bfloat16 g_WtHi[3][65536];
__device__ __nv_bfloat16 g_WtLo[3][65536];

__device__ __forceinline__ float elu_f(float x) { return x > 0.f ? x : expm1f(x); }

__device__ __forceinline__ uint32_t smem_u32(const void* p) {
    uint32_t a;
    asm("{ .reg .u64 t; cvta.to.shared.u64 t, %1; cvt.u32.u64 %0, t; }" : "=r"(a) : "l"(p));
    return a;
}
__device__ __forceinline__ uint32_t pack_bf2(__nv_bfloat16 a, __nv_bfloat16 b) {
    __nv_bfloat162 h2; h2.x = a; h2.y = b;
    return *reinterpret_cast<uint32_t*>(&h2);
}

#define LDSM4(r, addr) \
    asm volatile("ldmatrix.sync.aligned.m8n8.x4.shared.b16 {%0,%1,%2,%3}, [%4];" \
        : "=r"((r)[0]), "=r"((r)[1]), "=r"((r)[2]), "=r"((r)[3]) : "r"(addr))

#define MMA16816(d, a, b0, b1) \
    asm volatile("mma.sync.aligned.m16n8k16.row.col.f32.bf16.bf16.f32 " \
        "{%0,%1,%2,%3},{%4,%5,%6,%7},{%8,%9},{%0,%1,%2,%3};" \
        : "+f"((d)[0]), "+f"((d)[1]), "+f"((d)[2]), "+f"((d)[3]) \
        : "r"((a)[0]), "r"((a)[1]), "r"((a)[2]), "r"((a)[3]), "r"(b0), "r"(b1))

// ---------------- edge index extraction -------------------------------------
__global__ void build_idx_k(const float* __restrict__ rr, const float* __restrict__ rs) {
    int e = blockIdx.x * blockDim.x + threadIdx.x;
    if (e >= Ee) return;
    int r = 0, s = 0;
    for (int n = 0; n < Nn; n++) {
        if (rr[e*Nn + n] > 0.5f) r = n;
        if (rs[e*Nn + n] > 0.5f) s = n;
    }
    g_recv[e] = r;
    g_send[e] = s;
}

// ---------------- weight prep: transpose [k][n]->[n][k] + bf16 split --------
__global__ void prep_wt_k(const float* __restrict__ W,
                          __nv_bfloat16* __restrict__ Hi, __nv_bfloat16* __restrict__ Lo) {
    __shared__ float t[32][33];
    int k0 = blockIdx.x * 32, n0 = blockIdx.y * 32;
    int tx = threadIdx.x, ty = threadIdx.y;
    t[ty][tx] = W[(k0 + ty) * 256 + n0 + tx];
    __syncthreads();
    float v = t[tx][ty];            // element (k = k0+tx, n = n0+ty)
    __nv_bfloat16 h = __float2bfloat16(v);
    __nv_bfloat16 l = __float2bfloat16(v - __bfloat162float(h));
    Hi[(n0 + ty) * 256 + k0 + tx] = h;
    Lo[(n0 + ty) * 256 + k0 + tx] = l;
}

// ---------------- big tensor-core GEMM via mma.sync bf16 split --------------
// CTA: 128 rows x 128 cols, K=256 in 8 chunks of 32. 2 CTAs/SM.
// AMODE 0: A = Amat
// AMODE 1: A = ELU(As[s]+Ar[r]+b1)
// AMODE 2: A = ELU(Amat + As[s]+Ar[r]+b1), plus BN partial stats in epilogue
#define AHI 0
#define ALO 10240
#define BHI 20480
#define BLO 30720
#define SMTOT 40960

template<int AMODE>
__global__ __launch_bounds__(256, 2)
void gemm_tc(const float* __restrict__ Amat,
             const __nv_bfloat16* __restrict__ WtHi, const __nv_bfloat16* __restrict__ WtLo,
             const float* __restrict__ As_, const float* __restrict__ Ar_,
             const float* __restrict__ b1,
             const float* __restrict__ bias, int do_elu,
             float* __restrict__ C)
{
    __shared__ char sm[SMTOT];
    __shared__ int sidx[128], ridx[128];

    const int tid  = threadIdx.x;
    const int lane = tid & 31, w = tid >> 5;
    const int row0 = blockIdx.x * 128;
    const int nbase = blockIdx.y * 128;
    const uint32_t sbase = smem_u32(sm);

    if (AMODE != 0 && tid < 128) {
        int row = row0 + tid;
        int b = row / Ee, e = row - b * Ee;
        sidx[tid] = (b * Nn + g_send[e]) * Hh;
        ridx[tid] = (b * Nn + g_recv[e]) * Hh;
    }
    __syncthreads();

    // per-warp tile origin
    const int m0w = (w & 3) * 32;
    const int n0w = (w >> 2) * 64;
    // ldmatrix lane address components
    const int laneA_row = (lane & 7) + ((lane >> 3) & 1) * 8;
    const int laneA_k   = ((lane >> 4) & 1) * 8;
    const int laneB_row = (lane & 7) + ((lane >> 4) & 1) * 8;
    const int laneB_k   = ((lane >> 3) & 1) * 8;

    uint32_t aBase[2], bBase[4];
    #pragma unroll
    for (int i = 0; i < 2; i++)
        aBase[i] = sbase + (uint32_t)((m0w + i*16 + laneA_row) * 80 + laneA_k * 2);
    #pragma unroll
    for (int jp = 0; jp < 4; jp++)
        bBase[jp] = sbase + (uint32_t)(BHI + (n0w + jp*16 + laneB_row) * 80 + laneB_k * 2);

    float acc[16][4];
    #pragma unroll
    for (int t = 0; t < 16; t++) { acc[t][0]=0.f; acc[t][1]=0.f; acc[t][2]=0.f; acc[t][3]=0.f; }

    const int rowA  = tid >> 1;
    const int kh    = (tid & 1) * 16;
    const int rowB  = tid >> 1;
    const int halfB = tid & 1;

    #pragma unroll 1
    for (int c = 0; c < 8; ++c) {
        __syncthreads();   // previous chunk's mma done: smem reusable

        // ---- A: inline load + combine + ELU + bf16 split, store to smem
        {
            const int k0c = c * 32 + kh;
            #pragma unroll
            for (int half = 0; half < 2; ++half) {
                int kk = k0c + half * 8;
                float v[8];
                if (AMODE == 0) {
                    float4 a0 = *(const float4*)(Amat + (size_t)(row0 + rowA) * 256 + kk);
                    float4 a1 = *(const float4*)(Amat + (size_t)(row0 + rowA) * 256 + kk + 4);
                    v[0]=a0.x; v[1]=a0.y; v[2]=a0.z; v[3]=a0.w;
                    v[4]=a1.x; v[5]=a1.y; v[6]=a1.z; v[7]=a1.w;
                } else {
                    float4 s0 = *(const float4*)(As_ + sidx[rowA] + kk);
                    float4 s1 = *(const float4*)(As_ + sidx[rowA] + kk + 4);
                    float4 r0 = *(const float4*)(Ar_ + ridx[rowA] + kk);
                    float4 r1 = *(const float4*)(Ar_ + ridx[rowA] + kk + 4);
                    float4 c0 = *(const float4*)(b1 + kk);
                    float4 c1 = *(const float4*)(b1 + kk + 4);
                    v[0]=s0.x+r0.x+c0.x; v[1]=s0.y+r0.y+c0.y;
                    v[2]=s0.z+r0.z+c0.z; v[3]=s0.w+r0.w+c0.w;
                    v[4]=s1.x+r1.x+c1.x; v[5]=s1.y+r1.y+c1.y;
                    v[6]=s1.z+r1.z+c1.z; v[7]=s1.w+r1.w+c1.w;
                    if (AMODE == 2) {
                        float4 p0 = *(const float4*)(Amat + (size_t)(row0 + rowA) * 256 + kk);
                        float4 p1 = *(const float4*)(Amat + (size_t)(row0 + rowA) * 256 + kk + 4);
                        v[0]+=p0.x; v[1]+=p0.y; v[2]+=p0.z; v[3]+=p0.w;
                        v[4]+=p1.x; v[5]+=p1.y; v[6]+=p1.z; v[7]+=p1.w;
                    }
                    #pragma unroll
                    for (int q = 0; q < 8; q++) v[q] = elu_f(v[q]);
                }
                uint32_t hp[4], lp[4];
                #pragma unroll
                for (int q = 0; q < 4; q++) {
                    float f0 = v[2*q], f1 = v[2*q+1];
                    __nv_bfloat16 h0 = __float2bfloat16(f0), h1 = __float2bfloat16(f1);
                    __nv_bfloat16 l0 = __float2bfloat16(f0 - __bfloat162float(h0));
                    __nv_bfloat16 l1 = __float2bfloat16(f1 - __bfloat162float(h1));
                    hp[q] = pack_bf2(h0, h1);
                    lp[q] = pack_bf2(l0, l1);
                }
                int boff = rowA * 80 + kh * 2 + half * 16;
                *(uint4*)(sm + AHI + boff) = make_uint4(hp[0], hp[1], hp[2], hp[3]);
                *(uint4*)(sm + ALO + boff) = make_uint4(lp[0], lp[1], lp[2], lp[3]);
            }
        }
        // ---- B: straight copy from pre-split images
        {
            const uint4* gsh = (const uint4*)(WtHi + (size_t)(nbase + rowB) * 256 + c * 32 + halfB * 16);
            const uint4* gsl = (const uint4*)(WtLo + (size_t)(nbase + rowB) * 256 + c * 32 + halfB * 16);
            uint4 h0 = gsh[0], h1 = gsh[1], l0 = gsl[0], l1 = gsl[1];
            int boff = rowB * 80 + halfB * 32;
            *(uint4*)(sm + BHI + boff)      = h0;
            *(uint4*)(sm + BHI + boff + 16) = h1;
            *(uint4*)(sm + BLO + boff)      = l0;
            *(uint4*)(sm + BLO + boff + 16) = l1;
        }
        __syncthreads();

        // ---- mma over this 32-k chunk
        #pragma unroll
        for (int ks = 0; ks < 2; ++ks) {
            uint32_t ah[2][4], al[2][4];
            #pragma unroll
            for (int i = 0; i < 2; i++) {
                LDSM4(ah[i], aBase[i] + AHI + ks * 32);
                LDSM4(al[i], aBase[i] + ALO + ks * 32);
            }
            #pragma unroll
            for (int jp = 0; jp < 4; jp++) {
                uint32_t bh4[4], bl4[4];
                LDSM4(bh4, bBase[jp] + ks * 32);
                LDSM4(bl4, bBase[jp] + 10240 + ks * 32);
                // hi*hi for all 4 acc tiles of this jp
                MMA16816(acc[0*8+2*jp],   ah[0], bh4[0], bh4[1]);
                MMA16816(acc[0*8+2*jp+1], ah[0], bh4[2], bh4[3]);
                MMA16816(acc[1*8+2*jp],   ah[1], bh4[0], bh4[1]);
                MMA16816(acc[1*8+2*jp+1], ah[1], bh4[2], bh4[3]);
                // hi*lo
                MMA16816(acc[0*8+2*jp],   ah[0], bl4[0], bl4[1]);
                MMA16816(acc[0*8+2*jp+1], ah[0], bl4[2], bl4[3]);
                MMA16816(acc[1*8+2*jp],   ah[1], bl4[0], bl4[1]);
                MMA16816(acc[1*8+2*jp+1], ah[1], bl4[2], bl4[3]);
                // lo*hi
                MMA16816(acc[0*8+2*jp],   al[0], bh4[0], bh4[1]);
                MMA16816(acc[0*8+2*jp+1], al[0], bh4[2], bh4[3]);
                MMA16816(acc[1*8+2*jp],   al[1], bh4[0], bh4[1]);
                MMA16816(acc[1*8+2*jp+1], al[1], bh4[2], bh4[3]);
            }
        }
    }

    // ---- epilogue: bias + ELU, fp32 stores (+ BN partials for AMODE 2)
    const int g  = lane >> 2;
    const int tg = lane & 3;
    float cs[16], cq[16];
    if (AMODE == 2) {
        #pragma unroll
        for (int t = 0; t < 16; ++t) { cs[t] = 0.f; cq[t] = 0.f; }
    }
    #pragma unroll
    for (int i = 0; i < 2; i++) {
        #pragma unroll
        for (int j = 0; j < 8; j++) {
            int colg = nbase + n0w + j*8 + tg*2;
            float b0v = 0.f, b1v = 0.f;
            if (bias) { b0v = __ldg(bias + colg); b1v = __ldg(bias + colg + 1); }
            float* q = acc[i*8+j];
            int rlo = row0 + m0w + i*16 + g;
            int rhi = rlo + 8;
            float2 o0, o1;
            o0.x = q[0] + b0v; o0.y = q[1] + b1v;
            o1.x = q[2] + b0v; o1.y = q[3] + b1v;
            if (do_elu) {
                o0.x = elu_f(o0.x); o0.y = elu_f(o0.y);
                o1.x = elu_f(o1.x); o1.y = elu_f(o1.y);
            }
            if (AMODE == 2) {
                cs[j*2+0] += o0.x + o1.x;
                cs[j*2+1] += o0.y + o1.y;
                cq[j*2+0] += o0.x*o0.x + o1.x*o1.x;
                cq[j*2+1] += o0.y*o0.y + o1.y*o1.y;
            }
            *(float2*)(C + (size_t)rlo * 256 + colg) = o0;
            *(float2*)(C + (size_t)rhi * 256 + colg) = o1;
        }
    }

    if (AMODE == 2) {
        // reduce over the 8 row-groups (lanes differing in g): xor 4,8,16
        #pragma unroll
        for (int t = 0; t < 16; ++t) {
            #pragma unroll
            for (int o = 4; o <= 16; o <<= 1) {
                cs[t] += __shfl_xor_sync(0xffffffffu, cs[t], o);
                cq[t] += __shfl_xor_sync(0xffffffffu, cq[t], o);
            }
        }
        __syncthreads();                 // all MMAs done; sm reusable
        float* sps = (float*)sm;         // [8 warps][64 cols][2]
        if (lane < 4) {
            #pragma unroll
            for (int j = 0; j < 8; ++j) {
                #pragma unroll
                for (int par = 0; par < 2; ++par) {
                    int col = j*8 + lane*2 + par;
                    sps[(w*64 + col)*2 + 0] = cs[j*2+par];
                    sps[(w*64 + col)*2 + 1] = cq[j*2+par];
                }
            }
        }
        __syncthreads();
        // 256 threads: deterministic cross-warp reduce, write per-CTA partial
        int strip = tid >> 7, col = (tid >> 1) & 63, stat = tid & 1;
        float a2 = 0.f;
        #pragma unroll
        for (int wi = 0; wi < 4; ++wi)
            a2 += sps[((strip*4 + wi)*64 + col)*2 + stat];
        int ch = nbase + strip*64 + col;
        g_p3[((size_t)blockIdx.x * 256 + ch)*2 + stat] = a2;
    }
}

// ---------------- small node-level SIMT GEMM (M=3200) -----------------------
__global__ __launch_bounds__(256)
void gemm_node(const float* __restrict__ A, int lda, int K,
               const float* __restrict__ W, const float* __restrict__ bias,
               int do_elu, float* __restrict__ C)
{
    __shared__ float sA[16][65];
    __shared__ float sB[16][64];
    const int row0 = blockIdx.x * 64;
    const int col0 = blockIdx.y * 64;
    const int tid  = threadIdx.x;
    const int ty   = tid >> 4, tx = tid & 15;
    float acc[4][4] = {};
    for (int kt = 0; kt < K; kt += 16) {
        #pragma unroll
        for (int i = 0; i < 4; i++) {
            int idx = tid + i * 256;
            int m = idx >> 4, k = idx & 15;
            int kk = kt + k;
            sA[k][m] = (kk < K) ? A[(size_t)(row0 + m) * lda + kk] : 0.f;
        }
        #pragma unroll
        for (int i = 0; i < 4; i++) {
            int idx = tid + i * 256;
            int k = idx >> 6, n = idx & 63;
            int kk = kt + k;
            sB[k][n] = (kk < K) ? W[(size_t)kk * 256 + col0 + n] : 0.f;
        }
        __syncthreads();
        #pragma unroll
        for (int k = 0; k < 16; k++) {
            float a[4], b[4];
            #pragma unroll
            for (int i = 0; i < 4; i++) a[i] = sA[k][ty*4 + i];
            #pragma unroll
            for (int j = 0; j < 4; j++) b[j] = sB[k][tx*4 + j];
            #pragma unroll
            for (int i = 0; i < 4; i++)
                #pragma unroll
                for (int j = 0; j < 4; j++)
                    acc[i][j] += a[i] * b[j];
        }
        __syncthreads();
    }
    #pragma unroll
    for (int i = 0; i < 4; i++) {
        int m = row0 + ty*4 + i;
        #pragma unroll
        for (int j = 0; j < 4; j++) {
            int n = col0 + tx*4 + j;
            float v = acc[i][j];
            if (bias) v += bias[n];
            if (do_elu) v = elu_f(v);
            C[(size_t)m * 256 + n] = v;
        }
    }
}

// ---------------- merged dual node GEMM: same A, two weight mats ------------
__global__ __launch_bounds__(256)
void gemm_node2(const float* __restrict__ A,
                const float* __restrict__ Wa, const float* __restrict__ Wb,
                float* __restrict__ Ca, float* __restrict__ Cb)
{
    const float* W = (blockIdx.y < 4) ? Wa : Wb;
    float* C       = (blockIdx.y < 4) ? Ca : Cb;
    const int col0 = (blockIdx.y & 3) * 64;
    __shared__ float sA[16][65];
    __shared__ float sB[16][64];
    const int row0 = blockIdx.x * 64;
    const int tid  = threadIdx.x;
    const int ty   = tid >> 4, tx = tid & 15;
    float acc[4][4] = {};
    for (int kt = 0; kt < 256; kt += 16) {
        #pragma unroll
        for (int i = 0; i < 4; i++) {
            int idx = tid + i * 256;
            int m = idx >> 4, k = idx & 15;
            sA[k][m] = A[(size_t)(row0 + m) * 256 + kt + k];
        }
        #pragma unroll
        for (int i = 0; i < 4; i++) {
            int idx = tid + i * 256;
            int k = idx >> 6, n = idx & 63;
            sB[k][n] = W[(size_t)(kt + k) * 256 + col0 + n];
        }
        __syncthreads();
        #pragma unroll
        for (int k = 0; k < 16; k++) {
            float a[4], b[4];
            #pragma unroll
            for (int i = 0; i < 4; i++) a[i] = sA[k][ty*4 + i];
            #pragma unroll
            for (int j = 0; j < 4; j++) b[j] = sB[k][tx*4 + j];
            #pragma unroll
            for (int i = 0; i < 4; i++)
                #pragma unroll
                for (int j = 0; j < 4; j++)
                    acc[i][j] += a[i] * b[j];
        }
        __syncthreads();
    }
    #pragma unroll
    for (int i = 0; i < 4; i++) {
        int m = row0 + ty*4 + i;
        #pragma unroll
        for (int j = 0; j < 4; j++)
            C[(size_t)m * 256 + col0 + tx*4 + j] = acc[i][j];
    }
}

// ---------------- edge2node: contiguous 99-edge segment mean ----------------
__global__ void edge2node_k(const float* __restrict__ x, float* __restrict__ out) {
    int nodeRow = blockIdx.x;
    int h = threadIdx.x;
    int b = nodeRow / Nn, n = nodeRow - b * Nn;
    const float* base = x + (size_t)(b * Ee + n * 99) * Hh + h;
    float s = 0.f;
    #pragma unroll 3
    for (int r = 0; r < 99; r++) s += base[(size_t)r * Hh];
    out[(size_t)nodeRow * Hh + h] = s * (1.0f / 9900.0f);
}

// ---------------- BN finalize (reads fused per-CTA partials) ----------------
__global__ void bn_fin2(const float* __restrict__ gamma, const float* __restrict__ beta,
                        const float* __restrict__ W, const float* __restrict__ fb) {
    int ch = threadIdx.x;
    double s = 0.0, q = 0.0;
    for (int bx = 0; bx < NCTA; bx++) {
        s += (double)g_p3[((size_t)bx*256 + ch)*2 + 0];
        q += (double)g_p3[((size_t)bx*256 + ch)*2 + 1];
    }
    double m = s / (double)BE;
    double v = q / (double)BE - m * m;
    float sc = (float)(rsqrt(v + 1e-5) * (double)gamma[ch]);
    float sh = beta[ch] - (float)m * sc;
    float w0 = W[ch*2 + 0], w1 = W[ch*2 + 1];
    g_fcW[ch*2 + 0] = sc * w0;
    g_fcW[ch*2 + 1] = sc * w1;
    __shared__ float r0s[256], r1s[256];
    r0s[ch] = sh * w0;
    r1s[ch] = sh * w1;
    __syncthreads();
    for (int st = 128; st > 0; st >>= 1) {
        if (ch < st) { r0s[ch] += r0s[ch + st]; r1s[ch] += r1s[ch + st]; }
        __syncthreads();
    }
    if (ch == 0) { g_fcB[0] = r0s[0] + fb[0]; g_fcB[1] = r1s[0] + fb[1]; }
}

// ---------------- final fc (folded BN): warp per row ------------------------
__global__ void fc_k(const float* __restrict__ y, float* __restrict__ out) {
    int gwarp = (blockIdx.x * blockDim.x + threadIdx.x) >> 5;
    int lane  = threadIdx.x & 31;
    if (gwarp >= BE) return;
    const float* row = y + (size_t)gwarp * Hh;
    float a0 = 0.f, a1 = 0.f;
    #pragma unroll
    for (int i = lane; i < Hh; i += 32) {
        float v = row[i];
        a0 += v * g_fcW[i*2 + 0];
        a1 += v * g_fcW[i*2 + 1];
    }
    #pragma unroll
    for (int o = 16; o > 0; o >>= 1) {
        a0 += __shfl_down_sync(0xffffffffu, a0, o);
        a1 += __shfl_down_sync(0xffffffffu, a1, o);
    }
    if (lane == 0) {
        out[(size_t)gwarp * 2 + 0] = a0 + g_fcB[0];
        out[(size_t)gwarp * 2 + 1] = a1 + g_fcB[1];
    }
}

// ---------------------------------------------------------------------------
extern "C" void kernel_launch(void* const* d_in, const int* in_sizes, int n_in,
                              void* d_out, int out_size) {
    const float* inputs  = (const float*)d_in[0];
    const float* rel_rec = (const float*)d_in[1];
    const float* rel_snd = (const float*)d_in[2];
    const float* m1W1 = (const float*)d_in[3];  const float* m1b1 = (const float*)d_in[4];
    const float* m1W2 = (const float*)d_in[5];  const float* m1b2 = (const float*)d_in[6];
    const float* m2W1 = (const float*)d_in[7];  const float* m2b1 = (const float*)d_in[8];
    const float* m2W2 = (const float*)d_in[9];  const float* m2b2 = (const float*)d_in[10];
    const float* m3W1 = (const float*)d_in[11]; const float* m3b1 = (const float*)d_in[12];
    const float* m3W2 = (const float*)d_in[13]; const float* m3b2 = (const float*)d_in[14];
    const float* m4W1 = (const float*)d_in[15]; const float* m4b1 = (const float*)d_in[16];
    const float* m4W2 = (const float*)d_in[17]; const float* m4b2 = (const float*)d_in[18];
    const float* gmma = (const float*)d_in[19]; const float* beta = (const float*)d_in[20];
    const float* fcW  = (const float*)d_in[21]; const float* fcb  = (const float*)d_in[22];
    float* out = (float*)d_out;

    float *h1, *na, *nb, *as_, *ar_, *xskip, *pre, *y4;
    __nv_bfloat16 *wth, *wtl;
    cudaGetSymbolAddress((void**)&h1, g_h1);
    cudaGetSymbolAddress((void**)&na, g_na);
    cudaGetSymbolAddress((void**)&nb, g_nb);
    cudaGetSymbolAddress((void**)&as_, g_as);
    cudaGetSymbolAddress((void**)&ar_, g_ar);
    cudaGetSymbolAddress((void**)&xskip, g_xskip);
    cudaGetSymbolAddress((void**)&pre, g_pre);
    cudaGetSymbolAddress((void**)&y4, g_y4);
    cudaGetSymbolAddress((void**)&wth, g_WtHi);
    cudaGetSymbolAddress((void**)&wtl, g_WtLo);

    dim3 gN(BNr / 64, 4);
    dim3 gN2(BNr / 64, 8);
    dim3 gE(NCTA, 2);
    dim3 tb(32, 32);
    dim3 tg(8, 8);

    // edge index tables + weight prep (transpose + bf16 split)
    build_idx_k<<<(Ee + 127) / 128, 128>>>(rel_rec, rel_snd);
    prep_wt_k<<<tg, tb>>>(m2W2,             wth + 0 * 65536, wtl + 0 * 65536);
    prep_wt_k<<<tg, tb>>>(m4W1 + 512 * 256, wth + 1 * 65536, wtl + 1 * 65536);
    prep_wt_k<<<tg, tb>>>(m4W2,             wth + 2 * 65536, wtl + 2 * 65536);

    // mlp1 (node level)
    gemm_node<<<gN, 256>>>(inputs, FIN, FIN, m1W1, m1b1, 1, na);
    gemm_node<<<gN, 256>>>(na, Hh, Hh, m1W2, m1b2, 1, h1);

    // node projections for mlp2 layer1 (send + recv halves, one launch)
    gemm_node2<<<gN2, 256>>>(h1, m2W1, m2W1 + 256*256, as_, ar_);

    // big GEMM #1 (tensor): xskip = ELU(ELU(as[s]+ar[r]+b1) @ W2 + b2)
    gemm_tc<1><<<gE, 256>>>(nullptr, wth + 0 * 65536, wtl + 0 * 65536,
                            as_, ar_, m2b1, m2b2, 1, xskip);

    // edge2node + mlp3 (node level)
    edge2node_k<<<BNr, 256>>>(xskip, na);
    gemm_node<<<gN, 256>>>(na, Hh, Hh, m3W1, m3b1, 1, nb);
    gemm_node<<<gN, 256>>>(nb, Hh, Hh, m3W2, m3b2, 1, h1);

    // node projections for mlp4 layer1
    gemm_node2<<<gN2, 256>>>(h1, m4W1, m4W1 + 256*256, as_, ar_);

    // big GEMM #2 (tensor): pre = xskip @ W4_1[512:768]
    gemm_tc<0><<<gE, 256>>>(xskip, wth + 1 * 65536, wtl + 1 * 65536,
                            nullptr, nullptr, nullptr, nullptr, 0, pre);

    // big GEMM #3 (tensor): y4 = ELU(ELU(pre + as[s]+ar[r]+b1) @ W4_2 + b2)
    //                        + fused per-CTA BN partial stats
    gemm_tc<2><<<gE, 256>>>(pre, wth + 2 * 65536, wtl + 2 * 65536,
                            as_, ar_, m4b1, m4b2, 1, y4);

    // BN finalize (fold into fc), final fc
    bn_fin2<<<1, 256>>>(gmma, beta, fcW, fcb);
    fc_k<<<(BE * 32 + 255) / 256, 256>>>(y4, out);
}

// round 5
// speedup vs baseline: 2.0630x; 1.0351x over previous
#include <cuda_runtime.h>
#include <cuda_bf16.h>
#include <math.h>
#include <cstdint>

#define Bsz 32
#define Nn  100
#define Ee  9900
#define Hh  256
#define FIN 200
#define BE  (Bsz*Ee)    // 316800
#define BNr (Bsz*Nn)    // 3200
#define NCTA (BE/128)   // 2475

// ---------------- scratch (static device globals) ---------------------------
__device__ float g_h1[BNr*Hh];
__device__ float g_na[BNr*Hh];
__device__ float g_nb[BNr*Hh];
__device__ float g_as[BNr*Hh];
__device__ float g_ar[BNr*Hh];
__device__ float g_xskip[(size_t)BE*Hh];
__device__ float g_pre[(size_t)BE*Hh];
__device__ float g_y4[(size_t)BE*Hh];
__device__ int   g_send[Ee];
__device__ int   g_recv[Ee];
__device__ float g_p3[(size_t)NCTA*256*2];   // per-CTA BN partials (sum, sumsq)
__device__ double g_chS[256], g_chQ[256];
__device__ float g_fcW[Hh*2];
__device__ float g_fcB[2];
// transposed + bf16-split weight images: [n][k] layout, 3 mats
__device__ __nv_bfloat16 g_WtHi[3][65536];
__device__ __nv_bfloat16 g_WtLo[3][65536];

__device__ __forceinline__ float elu_f(float x) { return x > 0.f ? x : expm1f(x); }

__device__ __forceinline__ uint32_t smem_u32(const void* p) {
    uint32_t a;
    asm("{ .reg .u64 t; cvta.to.shared.u64 t, %1; cvt.u32.u64 %0, t; }" : "=r"(a) : "l"(p));
    return a;
}
__device__ __forceinline__ uint32_t pack_bf2(__nv_bfloat16 a, __nv_bfloat16 b) {
    __nv_bfloat162 h2; h2.x = a; h2.y = b;
    return *reinterpret_cast<uint32_t*>(&h2);
}

#define LDSM4(r, addr) \
    asm volatile("ldmatrix.sync.aligned.m8n8.x4.shared.b16 {%0,%1,%2,%3}, [%4];" \
        : "=r"((r)[0]), "=r"((r)[1]), "=r"((r)[2]), "=r"((r)[3]) : "r"(addr))

#define MMA16816(d, a, b0, b1) \
    asm volatile("mma.sync.aligned.m16n8k16.row.col.f32.bf16.bf16.f32 " \
        "{%0,%1,%2,%3},{%4,%5,%6,%7},{%8,%9},{%0,%1,%2,%3};" \
        : "+f"((d)[0]), "+f"((d)[1]), "+f"((d)[2]), "+f"((d)[3]) \
        : "r"((a)[0]), "r"((a)[1]), "r"((a)[2]), "r"((a)[3]), "r"(b0), "r"(b1))

#define CP16(dst, src) \
    asm volatile("cp.async.ca.shared.global [%0], [%1], 16;" :: "r"(dst), "l"(src))
#define CP_COMMIT() asm volatile("cp.async.commit_group;" ::: "memory")
#define CP_WAIT0()  asm volatile("cp.async.wait_group 0;" ::: "memory")

// ---------------- edge index extraction -------------------------------------
__global__ void build_idx_k(const float* __restrict__ rr, const float* __restrict__ rs) {
    int e = blockIdx.x * blockDim.x + threadIdx.x;
    if (e >= Ee) return;
    int r = 0, s = 0;
    for (int n = 0; n < Nn; n++) {
        if (rr[e*Nn + n] > 0.5f) r = n;
        if (rs[e*Nn + n] > 0.5f) s = n;
    }
    g_recv[e] = r;
    g_send[e] = s;
}

// ---------------- weight prep: transpose [k][n]->[n][k] + bf16 split --------
__global__ void prep_wt_k(const float* __restrict__ W,
                          __nv_bfloat16* __restrict__ Hi, __nv_bfloat16* __restrict__ Lo) {
    __shared__ float t[32][33];
    int k0 = blockIdx.x * 32, n0 = blockIdx.y * 32;
    int tx = threadIdx.x, ty = threadIdx.y;
    t[ty][tx] = W[(k0 + ty) * 256 + n0 + tx];
    __syncthreads();
    float v = t[tx][ty];            // element (k = k0+tx, n = n0+ty)
    __nv_bfloat16 h = __float2bfloat16(v);
    __nv_bfloat16 l = __float2bfloat16(v - __bfloat162float(h));
    Hi[(n0 + ty) * 256 + k0 + tx] = h;
    Lo[(n0 + ty) * 256 + k0 + tx] = l;
}

// ---------------- big tensor-core GEMM, pipelined double-buffer -------------
// CTA: 128 rows x 128 cols, K=256 in 8 chunks of 32.
// AMODE 0: A = Amat
// AMODE 1: A = ELU(As[s]+Ar[r]+b1)
// AMODE 2: A = ELU(Amat + As[s]+Ar[r]+b1), plus BN partials in epilogue
#define AHI 0
#define ALO 10240
#define BHI 20480
#define BLO 30720
#define BUFSZ 40960

template<int AMODE>
__global__ __launch_bounds__(256, 1)
void gemm_tc(const float* __restrict__ Amat,
             const __nv_bfloat16* __restrict__ WtHi, const __nv_bfloat16* __restrict__ WtLo,
             const float* __restrict__ As_, const float* __restrict__ Ar_,
             const float* __restrict__ b1,
             const float* __restrict__ bias, int do_elu,
             float* __restrict__ C)
{
    extern __shared__ char sm[];
    __shared__ int sidx[128], ridx[128];

    const int tid  = threadIdx.x;
    const int lane = tid & 31, w = tid >> 5;
    const int row0 = blockIdx.x * 128;
    const int nbase = blockIdx.y * 128;
    const uint32_t sbase = smem_u32(sm);

    if (AMODE != 0 && tid < 128) {
        int row = row0 + tid;
        int b = row / Ee, e = row - b * Ee;
        sidx[tid] = (b * Nn + g_send[e]) * Hh;
        ridx[tid] = (b * Nn + g_recv[e]) * Hh;
    }
    __syncthreads();

    // per-warp tile origin
    const int m0w = (w & 3) * 32;
    const int n0w = (w >> 2) * 64;
    // ldmatrix lane address components
    const int laneA_row = (lane & 7) + ((lane >> 3) & 1) * 8;
    const int laneA_k   = ((lane >> 4) & 1) * 8;
    const int laneB_row = (lane & 7) + ((lane >> 4) & 1) * 8;
    const int laneB_k   = ((lane >> 3) & 1) * 8;

    uint32_t aOff[2], bOff[4];
    #pragma unroll
    for (int i = 0; i < 2; i++)
        aOff[i] = (uint32_t)((m0w + i*16 + laneA_row) * 80 + laneA_k * 2);
    #pragma unroll
    for (int jp = 0; jp < 4; jp++)
        bOff[jp] = (uint32_t)(BHI + (n0w + jp*16 + laneB_row) * 80 + laneB_k * 2);

    float acc[16][4];
    #pragma unroll
    for (int t = 0; t < 16; t++) { acc[t][0]=0.f; acc[t][1]=0.f; acc[t][2]=0.f; acc[t][3]=0.f; }

    const int rowA  = tid >> 1;
    const int kh    = (tid & 1) * 16;
    const int rowB  = tid >> 1;
    const int halfB = tid & 1;
    const size_t arow = (size_t)(row0 + rowA) * 256;

    float4 pS[4], pR[4], pP[4];

    // issue A-source LDGs for chunk cc into regs (consumed later by STSA)
    #define LOADA(cc) do { \
        int kk0 = (cc) * 32 + kh; \
        if (AMODE == 0 || AMODE == 2) { \
            _Pragma("unroll") \
            for (int i = 0; i < 4; i++) \
                pP[i] = *(const float4*)(Amat + arow + kk0 + 4*i); \
        } \
        if (AMODE != 0) { \
            _Pragma("unroll") \
            for (int i = 0; i < 4; i++) { \
                pS[i] = *(const float4*)(As_ + sidx[rowA] + kk0 + 4*i); \
                pR[i] = *(const float4*)(Ar_ + ridx[rowA] + kk0 + 4*i); \
            } \
        } \
    } while (0)

    // combine + ELU + split + STS into buffer bf (chunk cc only for b1 offset)
    #define STSA(cc, bf) do { \
        int kk0 = (cc) * 32 + kh; \
        float v[16]; \
        _Pragma("unroll") \
        for (int i = 0; i < 4; i++) { \
            float4 t; \
            if (AMODE == 0) { \
                t = pP[i]; \
            } else { \
                float4 c4 = *(const float4*)(b1 + kk0 + 4*i); \
                t.x = pS[i].x + pR[i].x + c4.x; \
                t.y = pS[i].y + pR[i].y + c4.y; \
                t.z = pS[i].z + pR[i].z + c4.z; \
                t.w = pS[i].w + pR[i].w + c4.w; \
                if (AMODE == 2) { t.x += pP[i].x; t.y += pP[i].y; t.z += pP[i].z; t.w += pP[i].w; } \
                t.x = elu_f(t.x); t.y = elu_f(t.y); t.z = elu_f(t.z); t.w = elu_f(t.w); \
            } \
            v[4*i+0]=t.x; v[4*i+1]=t.y; v[4*i+2]=t.z; v[4*i+3]=t.w; \
        } \
        uint32_t hp[8], lp[8]; \
        _Pragma("unroll") \
        for (int q = 0; q < 8; q++) { \
            float f0 = v[2*q], f1 = v[2*q+1]; \
            __nv_bfloat16 h0 = __float2bfloat16(f0), h1 = __float2bfloat16(f1); \
            __nv_bfloat16 l0 = __float2bfloat16(f0 - __bfloat162float(h0)); \
            __nv_bfloat16 l1 = __float2bfloat16(f1 - __bfloat162float(h1)); \
            hp[q] = pack_bf2(h0, h1); \
            lp[q] = pack_bf2(l0, l1); \
        } \
        char* base = sm + (bf) * BUFSZ + rowA * 80 + kh * 2; \
        *(uint4*)(base + AHI)      = make_uint4(hp[0], hp[1], hp[2], hp[3]); \
        *(uint4*)(base + AHI + 16) = make_uint4(hp[4], hp[5], hp[6], hp[7]); \
        *(uint4*)(base + ALO)      = make_uint4(lp[0], lp[1], lp[2], lp[3]); \
        *(uint4*)(base + ALO + 16) = make_uint4(lp[4], lp[5], lp[6], lp[7]); \
    } while (0)

    // async-copy B chunk cc into buffer bf
    #define CPB(cc, bf) do { \
        uint32_t d = sbase + (bf) * BUFSZ + BHI + rowB * 80 + halfB * 32; \
        const char* sh = (const char*)(WtHi + (size_t)(nbase + rowB) * 256 + (cc) * 32 + halfB * 16); \
        const char* sl = (const char*)(WtLo + (size_t)(nbase + rowB) * 256 + (cc) * 32 + halfB * 16); \
        CP16(d, sh); CP16(d + 16, sh + 16); \
        CP16(d + (BLO - BHI), sl); CP16(d + (BLO - BHI) + 16, sl + 16); \
    } while (0)

    // ---- prologue: stage chunk 0 into buffer 0
    LOADA(0);
    CPB(0, 0);
    CP_COMMIT();
    STSA(0, 0);
    CP_WAIT0();
    __syncthreads();

    #pragma unroll 1
    for (int c = 0; c < 8; ++c) {
        const int cur = c & 1, nxt = cur ^ 1;
        if (c < 7) {
            LOADA(c + 1);
            CPB(c + 1, nxt);
            CP_COMMIT();
        }
        // ---- mma over chunk c (buffer cur)
        const uint32_t base = sbase + cur * BUFSZ;
        #pragma unroll
        for (int ks = 0; ks < 2; ++ks) {
            uint32_t ah[2][4], al[2][4];
            #pragma unroll
            for (int i = 0; i < 2; i++) {
                LDSM4(ah[i], base + aOff[i] + AHI + ks * 32);
                LDSM4(al[i], base + aOff[i] + ALO + ks * 32);
            }
            #pragma unroll
            for (int jp = 0; jp < 4; jp++) {
                uint32_t bh4[4], bl4[4];
                LDSM4(bh4, base + bOff[jp] + ks * 32);
                LDSM4(bl4, base + bOff[jp] + 10240 + ks * 32);
                MMA16816(acc[0*8+2*jp],   ah[0], bh4[0], bh4[1]);
                MMA16816(acc[0*8+2*jp+1], ah[0], bh4[2], bh4[3]);
                MMA16816(acc[1*8+2*jp],   ah[1], bh4[0], bh4[1]);
                MMA16816(acc[1*8+2*jp+1], ah[1], bh4[2], bh4[3]);
                MMA16816(acc[0*8+2*jp],   ah[0], bl4[0], bl4[1]);
                MMA16816(acc[0*8+2*jp+1], ah[0], bl4[2], bl4[3]);
                MMA16816(acc[1*8+2*jp],   ah[1], bl4[0], bl4[1]);
                MMA16816(acc[1*8+2*jp+1], ah[1], bl4[2], bl4[3]);
                MMA16816(acc[0*8+2*jp],   al[0], bh4[0], bh4[1]);
                MMA16816(acc[0*8+2*jp+1], al[0], bh4[2], bh4[3]);
                MMA16816(acc[1*8+2*jp],   al[1], bh4[0], bh4[1]);
                MMA16816(acc[1*8+2*jp+1], al[1], bh4[2], bh4[3]);
            }
        }
        if (c < 7) STSA(c + 1, nxt);
        CP_WAIT0();
        __syncthreads();
    }

    // ---- epilogue: bias + ELU, fp32 stores (+ BN partials for AMODE 2)
    const int g  = lane >> 2;
    const int tg = lane & 3;
    float cs[16], cq[16];
    if (AMODE == 2) {
        #pragma unroll
        for (int t = 0; t < 16; ++t) { cs[t] = 0.f; cq[t] = 0.f; }
    }
    #pragma unroll
    for (int i = 0; i < 2; i++) {
        #pragma unroll
        for (int j = 0; j < 8; j++) {
            int colg = nbase + n0w + j*8 + tg*2;
            float b0v = 0.f, b1v = 0.f;
            if (bias) { b0v = __ldg(bias + colg); b1v = __ldg(bias + colg + 1); }
            float* q = acc[i*8+j];
            int rlo = row0 + m0w + i*16 + g;
            int rhi = rlo + 8;
            float2 o0, o1;
            o0.x = q[0] + b0v; o0.y = q[1] + b1v;
            o1.x = q[2] + b0v; o1.y = q[3] + b1v;
            if (do_elu) {
                o0.x = elu_f(o0.x); o0.y = elu_f(o0.y);
                o1.x = elu_f(o1.x); o1.y = elu_f(o1.y);
            }
            if (AMODE == 2) {
                cs[j*2+0] += o0.x + o1.x;
                cs[j*2+1] += o0.y + o1.y;
                cq[j*2+0] += o0.x*o0.x + o1.x*o1.x;
                cq[j*2+1] += o0.y*o0.y + o1.y*o1.y;
            }
            *(float2*)(C + (size_t)rlo * 256 + colg) = o0;
            *(float2*)(C + (size_t)rhi * 256 + colg) = o1;
        }
    }

    if (AMODE == 2) {
        #pragma unroll
        for (int t = 0; t < 16; ++t) {
            #pragma unroll
            for (int o = 4; o <= 16; o <<= 1) {
                cs[t] += __shfl_xor_sync(0xffffffffu, cs[t], o);
                cq[t] += __shfl_xor_sync(0xffffffffu, cq[t], o);
            }
        }
        __syncthreads();
        float* sps = (float*)sm;         // [8 warps][64 cols][2]
        if (lane < 4) {
            #pragma unroll
            for (int j = 0; j < 8; ++j) {
                #pragma unroll
                for (int par = 0; par < 2; ++par) {
                    int col = j*8 + lane*2 + par;
                    sps[(w*64 + col)*2 + 0] = cs[j*2+par];
                    sps[(w*64 + col)*2 + 1] = cq[j*2+par];
                }
            }
        }
        __syncthreads();
        int strip = tid >> 7, col = (tid >> 1) & 63, stat = tid & 1;
        float a2 = 0.f;
        #pragma unroll
        for (int wi = 0; wi < 4; ++wi)
            a2 += sps[((strip*4 + wi)*64 + col)*2 + stat];
        int ch = nbase + strip*64 + col;
        g_p3[((size_t)blockIdx.x * 256 + ch)*2 + stat] = a2;
    }
    #undef LOADA
    #undef STSA
    #undef CPB
}

// ---------------- small node-level SIMT GEMM (M=3200) -----------------------
__global__ __launch_bounds__(256)
void gemm_node(const float* __restrict__ A, int lda, int K,
               const float* __restrict__ W, const float* __restrict__ bias,
               int do_elu, float* __restrict__ C)
{
    __shared__ float sA[16][65];
    __shared__ float sB[16][64];
    const int row0 = blockIdx.x * 64;
    const int col0 = blockIdx.y * 64;
    const int tid  = threadIdx.x;
    const int ty   = tid >> 4, tx = tid & 15;
    float acc[4][4] = {};
    for (int kt = 0; kt < K; kt += 16) {
        #pragma unroll
        for (int i = 0; i < 4; i++) {
            int idx = tid + i * 256;
            int m = idx >> 4, k = idx & 15;
            int kk = kt + k;
            sA[k][m] = (kk < K) ? A[(size_t)(row0 + m) * lda + kk] : 0.f;
        }
        #pragma unroll
        for (int i = 0; i < 4; i++) {
            int idx = tid + i * 256;
            int k = idx >> 6, n = idx & 63;
            int kk = kt + k;
            sB[k][n] = (kk < K) ? W[(size_t)kk * 256 + col0 + n] : 0.f;
        }
        __syncthreads();
        #pragma unroll
        for (int k = 0; k < 16; k++) {
            float a[4], b[4];
            #pragma unroll
            for (int i = 0; i < 4; i++) a[i] = sA[k][ty*4 + i];
            #pragma unroll
            for (int j = 0; j < 4; j++) b[j] = sB[k][tx*4 + j];
            #pragma unroll
            for (int i = 0; i < 4; i++)
                #pragma unroll
                for (int j = 0; j < 4; j++)
                    acc[i][j] += a[i] * b[j];
        }
        __syncthreads();
    }
    #pragma unroll
    for (int i = 0; i < 4; i++) {
        int m = row0 + ty*4 + i;
        #pragma unroll
        for (int j = 0; j < 4; j++) {
            int n = col0 + tx*4 + j;
            float v = acc[i][j];
            if (bias) v += bias[n];
            if (do_elu) v = elu_f(v);
            C[(size_t)m * 256 + n] = v;
        }
    }
}

// ---------------- merged dual node GEMM: same A, two weight mats ------------
__global__ __launch_bounds__(256)
void gemm_node2(const float* __restrict__ A,
                const float* __restrict__ Wa, const float* __restrict__ Wb,
                float* __restrict__ Ca, float* __restrict__ Cb)
{
    const float* W = (blockIdx.y < 4) ? Wa : Wb;
    float* C       = (blockIdx.y < 4) ? Ca : Cb;
    const int col0 = (blockIdx.y & 3) * 64;
    __shared__ float sA[16][65];
    __shared__ float sB[16][64];
    const int row0 = blockIdx.x * 64;
    const int tid  = threadIdx.x;
    const int ty   = tid >> 4, tx = tid & 15;
    float acc[4][4] = {};
    for (int kt = 0; kt < 256; kt += 16) {
        #pragma unroll
        for (int i = 0; i < 4; i++) {
            int idx = tid + i * 256;
            int m = idx >> 4, k = idx & 15;
            sA[k][m] = A[(size_t)(row0 + m) * 256 + kt + k];
        }
        #pragma unroll
        for (int i = 0; i < 4; i++) {
            int idx = tid + i * 256;
            int k = idx >> 6, n = idx & 63;
            sB[k][n] = W[(size_t)(kt + k) * 256 + col0 + n];
        }
        __syncthreads();
        #pragma unroll
        for (int k = 0; k < 16; k++) {
            float a[4], b[4];
            #pragma unroll
            for (int i = 0; i < 4; i++) a[i] = sA[k][ty*4 + i];
            #pragma unroll
            for (int j = 0; j < 4; j++) b[j] = sB[k][tx*4 + j];
            #pragma unroll
            for (int i = 0; i < 4; i++)
                #pragma unroll
                for (int j = 0; j < 4; j++)
                    acc[i][j] += a[i] * b[j];
        }
        __syncthreads();
    }
    #pragma unroll
    for (int i = 0; i < 4; i++) {
        int m = row0 + ty*4 + i;
        #pragma unroll
        for (int j = 0; j < 4; j++)
            C[(size_t)m * 256 + col0 + tx*4 + j] = acc[i][j];
    }
}

// ---------------- edge2node: contiguous 99-edge segment mean ----------------
__global__ void edge2node_k(const float* __restrict__ x, float* __restrict__ out) {
    int nodeRow = blockIdx.x;
    int h = threadIdx.x;
    int b = nodeRow / Nn, n = nodeRow - b * Nn;
    const float* base = x + (size_t)(b * Ee + n * 99) * Hh + h;
    float s = 0.f;
    #pragma unroll 3
    for (int r = 0; r < 99; r++) s += base[(size_t)r * Hh];
    out[(size_t)nodeRow * Hh + h] = s * (1.0f / 9900.0f);
}

// ---------------- BN partial reduce: parallel deterministic tree ------------
__global__ void bn_reduce_k() {
    int ch = blockIdx.x, t = threadIdx.x;
    double s = 0.0, q = 0.0;
    for (int bx = t; bx < NCTA; bx += 256) {
        s += (double)g_p3[((size_t)bx * 256 + ch) * 2 + 0];
        q += (double)g_p3[((size_t)bx * 256 + ch) * 2 + 1];
    }
    __shared__ double ss[256], sq[256];
    ss[t] = s; sq[t] = q;
    __syncthreads();
    for (int st = 128; st > 0; st >>= 1) {
        if (t < st) { ss[t] += ss[t + st]; sq[t] += sq[t + st]; }
        __syncthreads();
    }
    if (t == 0) { g_chS[ch] = ss[0]; g_chQ[ch] = sq[0]; }
}

// ---------------- BN finalize + fold into fc --------------------------------
__global__ void bn_fin3(const float* __restrict__ gamma, const float* __restrict__ beta,
                        const float* __restrict__ W, const float* __restrict__ fb) {
    int ch = threadIdx.x;
    double s = g_chS[ch], q = g_chQ[ch];
    double m = s / (double)BE;
    double v = q / (double)BE - m * m;
    float sc = (float)(rsqrt(v + 1e-5) * (double)gamma[ch]);
    float sh = beta[ch] - (float)m * sc;
    float w0 = W[ch*2 + 0], w1 = W[ch*2 + 1];
    g_fcW[ch*2 + 0] = sc * w0;
    g_fcW[ch*2 + 1] = sc * w1;
    __shared__ float r0s[256], r1s[256];
    r0s[ch] = sh * w0;
    r1s[ch] = sh * w1;
    __syncthreads();
    for (int st = 128; st > 0; st >>= 1) {
        if (ch < st) { r0s[ch] += r0s[ch + st]; r1s[ch] += r1s[ch + st]; }
        __syncthreads();
    }
    if (ch == 0) { g_fcB[0] = r0s[0] + fb[0]; g_fcB[1] = r1s[0] + fb[1]; }
}

// ---------------- final fc (folded BN): warp per row ------------------------
__global__ void fc_k(const float* __restrict__ y, float* __restrict__ out) {
    int gwarp = (blockIdx.x * blockDim.x + threadIdx.x) >> 5;
    int lane  = threadIdx.x & 31;
    if (gwarp >= BE) return;
    const float* row = y + (size_t)gwarp * Hh;
    float a0 = 0.f, a1 = 0.f;
    #pragma unroll
    for (int i = lane; i < Hh; i += 32) {
        float v = row[i];
        a0 += v * g_fcW[i*2 + 0];
        a1 += v * g_fcW[i*2 + 1];
    }
    #pragma unroll
    for (int o = 16; o > 0; o >>= 1) {
        a0 += __shfl_down_sync(0xffffffffu, a0, o);
        a1 += __shfl_down_sync(0xffffffffu, a1, o);
    }
    if (lane == 0) {
        out[(size_t)gwarp * 2 + 0] = a0 + g_fcB[0];
        out[(size_t)gwarp * 2 + 1] = a1 + g_fcB[1];
    }
}

// ---------------------------------------------------------------------------
extern "C" void kernel_launch(void* const* d_in, const int* in_sizes, int n_in,
                              void* d_out, int out_size) {
    const float* inputs  = (const float*)d_in[0];
    const float* rel_rec = (const float*)d_in[1];
    const float* rel_snd = (const float*)d_in[2];
    const float* m1W1 = (const float*)d_in[3];  const float* m1b1 = (const float*)d_in[4];
    const float* m1W2 = (const float*)d_in[5];  const float* m1b2 = (const float*)d_in[6];
    const float* m2W1 = (const float*)d_in[7];  const float* m2b1 = (const float*)d_in[8];
    const float* m2W2 = (const float*)d_in[9];  const float* m2b2 = (const float*)d_in[10];
    const float* m3W1 = (const float*)d_in[11]; const float* m3b1 = (const float*)d_in[12];
    const float* m3W2 = (const float*)d_in[13]; const float* m3b2 = (const float*)d_in[14];
    const float* m4W1 = (const float*)d_in[15]; const float* m4b1 = (const float*)d_in[16];
    const float* m4W2 = (const float*)d_in[17]; const float* m4b2 = (const float*)d_in[18];
    const float* gmma = (const float*)d_in[19]; const float* beta = (const float*)d_in[20];
    const float* fcW  = (const float*)d_in[21]; const float* fcb  = (const float*)d_in[22];
    float* out = (float*)d_out;

    float *h1, *na, *nb, *as_, *ar_, *xskip, *pre, *y4;
    __nv_bfloat16 *wth, *wtl;
    cudaGetSymbolAddress((void**)&h1, g_h1);
    cudaGetSymbolAddress((void**)&na, g_na);
    cudaGetSymbolAddress((void**)&nb, g_nb);
    cudaGetSymbolAddress((void**)&as_, g_as);
    cudaGetSymbolAddress((void**)&ar_, g_ar);
    cudaGetSymbolAddress((void**)&xskip, g_xskip);
    cudaGetSymbolAddress((void**)&pre, g_pre);
    cudaGetSymbolAddress((void**)&y4, g_y4);
    cudaGetSymbolAddress((void**)&wth, g_WtHi);
    cudaGetSymbolAddress((void**)&wtl, g_WtLo);

    const int DSMEM = 2 * BUFSZ;   // 81920
    cudaFuncSetAttribute(gemm_tc<0>, cudaFuncAttributeMaxDynamicSharedMemorySize, DSMEM);
    cudaFuncSetAttribute(gemm_tc<1>, cudaFuncAttributeMaxDynamicSharedMemorySize, DSMEM);
    cudaFuncSetAttribute(gemm_tc<2>, cudaFuncAttributeMaxDynamicSharedMemorySize, DSMEM);

    dim3 gN(BNr / 64, 4);
    dim3 gN2(BNr / 64, 8);
    dim3 gE(NCTA, 2);
    dim3 tb(32, 32);
    dim3 tg(8, 8);

    // edge index tables + weight prep (transpose + bf16 split)
    build_idx_k<<<(Ee + 127) / 128, 128>>>(rel_rec, rel_snd);
    prep_wt_k<<<tg, tb>>>(m2W2,             wth + 0 * 65536, wtl + 0 * 65536);
    prep_wt_k<<<tg, tb>>>(m4W1 + 512 * 256, wth + 1 * 65536, wtl + 1 * 65536);
    prep_wt_k<<<tg, tb>>>(m4W2,             wth + 2 * 65536, wtl + 2 * 65536);

    // mlp1 (node level)
    gemm_node<<<gN, 256>>>(inputs, FIN, FIN, m1W1, m1b1, 1, na);
    gemm_node<<<gN, 256>>>(na, Hh, Hh, m1W2, m1b2, 1, h1);

    // node projections for mlp2 layer1 (send + recv halves, one launch)
    gemm_node2<<<gN2, 256>>>(h1, m2W1, m2W1 + 256*256, as_, ar_);

    // big GEMM #1 (tensor): xskip = ELU(ELU(as[s]+ar[r]+b1) @ W2 + b2)
    gemm_tc<1><<<gE, 256, DSMEM>>>(nullptr, wth + 0 * 65536, wtl + 0 * 65536,
                                   as_, ar_, m2b1, m2b2, 1, xskip);

    // edge2node + mlp3 (node level)
    edge2node_k<<<BNr, 256>>>(xskip, na);
    gemm_node<<<gN, 256>>>(na, Hh, Hh, m3W1, m3b1, 1, nb);
    gemm_node<<<gN, 256>>>(nb, Hh, Hh, m3W2, m3b2, 1, h1);

    // node projections for mlp4 layer1
    gemm_node2<<<gN2, 256>>>(h1, m4W1, m4W1 + 256*256, as_, ar_);

    // big GEMM #2 (tensor): pre = xskip @ W4_1[512:768]
    gemm_tc<0><<<gE, 256, DSMEM>>>(xskip, wth + 1 * 65536, wtl + 1 * 65536,
                                   nullptr, nullptr, nullptr, nullptr, 0, pre);

    // big GEMM #3 (tensor): y4 = ELU(ELU(pre + as[s]+ar[r]+b1) @ W4_2 + b2)
    //                        + fused per-CTA BN partial stats
    gemm_tc<2><<<gE, 256, DSMEM>>>(pre, wth + 2 * 65536, wtl + 2 * 65536,
                                   as_, ar_, m4b1, m4b2, 1, y4);

    // BN reduce (parallel deterministic), finalize, final fc
    bn_reduce_k<<<256, 256>>>();
    bn_fin3<<<1, 256>>>(gmma, beta, fcW, fcb);
    fc_k<<<(BE * 32 + 255) / 256, 256>>>(y4, out);
}

// round 6
// speedup vs baseline: 3.0068x; 1.4575x over previous
#include <cuda_runtime.h>
#include <cuda_fp16.h>
#include <math.h>
#include <cstdint>

#define Bsz 32
#define Nn  100
#define Ee  9900
#define Hh  256
#define FIN 200
#define BE  (Bsz*Ee)    // 316800
#define BNr (Bsz*Nn)    // 3200
#define NCTA (BE/128)   // 2475

// ---------------- scratch (static device globals) ---------------------------
__device__ float g_h1[BNr*Hh];
__device__ float g_na[BNr*Hh];
__device__ float g_nb[BNr*Hh];
__device__ float g_as[BNr*Hh];
__device__ float g_ar[BNr*Hh];
__device__ float g_xskip[(size_t)BE*Hh];
__device__ float g_pre[(size_t)BE*Hh];
__device__ float g_y4[(size_t)BE*Hh];
__device__ int   g_send[Ee];
__device__ int   g_recv[Ee];
__device__ float g_p3[(size_t)NCTA*256*2];   // per-CTA BN partials (sum, sumsq)
__device__ double g_chS[256], g_chQ[256];
__device__ float g_fcW[Hh*2];
__device__ float g_fcB[2];
// transposed fp16-split weight images: [n][k] layout, 3 mats
__device__ __half g_WtHi[3][65536];
__device__ __half g_WtLo[3][65536];

__device__ __forceinline__ float elu_f(float x) { return x > 0.f ? x : expm1f(x); }

__device__ __forceinline__ uint32_t smem_u32(const void* p) {
    uint32_t a;
    asm("{ .reg .u64 t; cvta.to.shared.u64 t, %1; cvt.u32.u64 %0, t; }" : "=r"(a) : "l"(p));
    return a;
}
__device__ __forceinline__ uint32_t pack_h2(__half a, __half b) {
    __half2 h2 = __halves2half2(a, b);
    return *reinterpret_cast<uint32_t*>(&h2);
}

#define LDSM4(r, addr) \
    asm volatile("ldmatrix.sync.aligned.m8n8.x4.shared.b16 {%0,%1,%2,%3}, [%4];" \
        : "=r"((r)[0]), "=r"((r)[1]), "=r"((r)[2]), "=r"((r)[3]) : "r"(addr))

#define MMA16816(d, a, b0, b1) \
    asm volatile("mma.sync.aligned.m16n8k16.row.col.f32.f16.f16.f32 " \
        "{%0,%1,%2,%3},{%4,%5,%6,%7},{%8,%9},{%0,%1,%2,%3};" \
        : "+f"((d)[0]), "+f"((d)[1]), "+f"((d)[2]), "+f"((d)[3]) \
        : "r"((a)[0]), "r"((a)[1]), "r"((a)[2]), "r"((a)[3]), "r"(b0), "r"(b1))

#define CP16(dst, src) \
    asm volatile("cp.async.ca.shared.global [%0], [%1], 16;" :: "r"(dst), "l"(src))
#define CP_COMMIT() asm volatile("cp.async.commit_group;" ::: "memory")
#define CP_WAIT0()  asm volatile("cp.async.wait_group 0;" ::: "memory")

// ---------------- edge index extraction -------------------------------------
__global__ void build_idx_k(const float* __restrict__ rr, const float* __restrict__ rs) {
    int e = blockIdx.x * blockDim.x + threadIdx.x;
    if (e >= Ee) return;
    int r = 0, s = 0;
    for (int n = 0; n < Nn; n++) {
        if (rr[e*Nn + n] > 0.5f) r = n;
        if (rs[e*Nn + n] > 0.5f) s = n;
    }
    g_recv[e] = r;
    g_send[e] = s;
}

// ---------------- weight prep: transpose [k][n]->[n][k] + fp16 split --------
__global__ void prep_wt_k(const float* __restrict__ W,
                          __half* __restrict__ Hi, __half* __restrict__ Lo) {
    __shared__ float t[32][33];
    int k0 = blockIdx.x * 32, n0 = blockIdx.y * 32;
    int tx = threadIdx.x, ty = threadIdx.y;
    t[ty][tx] = W[(k0 + ty) * 256 + n0 + tx];
    __syncthreads();
    float v = t[tx][ty];            // element (k = k0+tx, n = n0+ty)
    __half h = __float2half_rn(v);
    __half l = __float2half_rn(v - __half2float(h));
    Hi[(n0 + ty) * 256 + k0 + tx] = h;
    Lo[(n0 + ty) * 256 + k0 + tx] = l;
}

// ---------------- big tensor-core GEMM: fp16 2-term, double-buffered --------
// CTA: 128 rows x 128 cols, K=256 in 8 chunks of 32, 2 CTAs/SM.
// AMODE 0: A = Amat
// AMODE 1: A = ELU(As[s]+Ar[r]+b1)
// AMODE 2: A = ELU(Amat + As[s]+Ar[r]+b1), plus BN partials in epilogue
#define AOF 0
#define BHI 10240
#define BLO 20480
#define BUFSZ 30720

template<int AMODE>
__global__ __launch_bounds__(256, 2)
void gemm_tc(const float* __restrict__ Amat,
             const __half* __restrict__ WtHi, const __half* __restrict__ WtLo,
             const float* __restrict__ As_, const float* __restrict__ Ar_,
             const float* __restrict__ b1,
             const float* __restrict__ bias, int do_elu,
             float* __restrict__ C)
{
    extern __shared__ char sm[];
    __shared__ int sidx[128], ridx[128];

    const int tid  = threadIdx.x;
    const int lane = tid & 31, w = tid >> 5;
    const int row0 = blockIdx.x * 128;
    const int nbase = blockIdx.y * 128;
    const uint32_t sbase = smem_u32(sm);

    if (AMODE != 0 && tid < 128) {
        int row = row0 + tid;
        int b = row / Ee, e = row - b * Ee;
        sidx[tid] = (b * Nn + g_send[e]) * Hh;
        ridx[tid] = (b * Nn + g_recv[e]) * Hh;
    }
    __syncthreads();

    // per-warp tile origin
    const int m0w = (w & 3) * 32;
    const int n0w = (w >> 2) * 64;
    // ldmatrix lane address components
    const int laneA_row = (lane & 7) + ((lane >> 3) & 1) * 8;
    const int laneA_k   = ((lane >> 4) & 1) * 8;
    const int laneB_row = (lane & 7) + ((lane >> 4) & 1) * 8;
    const int laneB_k   = ((lane >> 3) & 1) * 8;

    uint32_t aOff[2], bOff[4];
    #pragma unroll
    for (int i = 0; i < 2; i++)
        aOff[i] = (uint32_t)(AOF + (m0w + i*16 + laneA_row) * 80 + laneA_k * 2);
    #pragma unroll
    for (int jp = 0; jp < 4; jp++)
        bOff[jp] = (uint32_t)(BHI + (n0w + jp*16 + laneB_row) * 80 + laneB_k * 2);

    float acc[16][4];
    #pragma unroll
    for (int t = 0; t < 16; t++) { acc[t][0]=0.f; acc[t][1]=0.f; acc[t][2]=0.f; acc[t][3]=0.f; }

    const int rowA  = tid >> 1;
    const int kh    = (tid & 1) * 16;
    const int rowB  = tid >> 1;
    const int halfB = tid & 1;
    const size_t arow = (size_t)(row0 + rowA) * 256;

    // A: inline LDG -> combine -> ELU -> fp16 -> STS into buffer bf
    #define STSA(cc, bf) do { \
        int kk0 = (cc) * 32 + kh; \
        float v[16]; \
        _Pragma("unroll") \
        for (int i = 0; i < 4; i++) { \
            float4 t; \
            if (AMODE == 0) { \
                t = *(const float4*)(Amat + arow + kk0 + 4*i); \
            } else { \
                float4 s4 = *(const float4*)(As_ + sidx[rowA] + kk0 + 4*i); \
                float4 r4 = *(const float4*)(Ar_ + ridx[rowA] + kk0 + 4*i); \
                float4 c4 = *(const float4*)(b1 + kk0 + 4*i); \
                t.x = s4.x + r4.x + c4.x; \
                t.y = s4.y + r4.y + c4.y; \
                t.z = s4.z + r4.z + c4.z; \
                t.w = s4.w + r4.w + c4.w; \
                if (AMODE == 2) { \
                    float4 p4 = *(const float4*)(Amat + arow + kk0 + 4*i); \
                    t.x += p4.x; t.y += p4.y; t.z += p4.z; t.w += p4.w; \
                } \
                t.x = elu_f(t.x); t.y = elu_f(t.y); t.z = elu_f(t.z); t.w = elu_f(t.w); \
            } \
            v[4*i+0]=t.x; v[4*i+1]=t.y; v[4*i+2]=t.z; v[4*i+3]=t.w; \
        } \
        uint32_t hp[8]; \
        _Pragma("unroll") \
        for (int q = 0; q < 8; q++) \
            hp[q] = pack_h2(__float2half_rn(v[2*q]), __float2half_rn(v[2*q+1])); \
        char* base = sm + (bf) * BUFSZ + AOF + rowA * 80 + kh * 2; \
        *(uint4*)(base)      = make_uint4(hp[0], hp[1], hp[2], hp[3]); \
        *(uint4*)(base + 16) = make_uint4(hp[4], hp[5], hp[6], hp[7]); \
    } while (0)

    // B: async-copy pre-split fp16 images (hi + lo) into buffer bf
    #define CPB(cc, bf) do { \
        uint32_t d = sbase + (bf) * BUFSZ + BHI + rowB * 80 + halfB * 32; \
        const char* sh = (const char*)(WtHi + (size_t)(nbase + rowB) * 256 + (cc) * 32 + halfB * 16); \
        const char* sl = (const char*)(WtLo + (size_t)(nbase + rowB) * 256 + (cc) * 32 + halfB * 16); \
        CP16(d, sh); CP16(d + 16, sh + 16); \
        CP16(d + (BLO - BHI), sl); CP16(d + (BLO - BHI) + 16, sl + 16); \
    } while (0)

    // ---- prologue: stage chunk 0 into buffer 0
    STSA(0, 0);
    CPB(0, 0);
    CP_COMMIT();

    #pragma unroll 1
    for (int c = 0; c < 8; ++c) {
        const int cur = c & 1, nxt = cur ^ 1;
        CP_WAIT0();
        __syncthreads();          // buf cur complete; all warps done with buf nxt
        if (c < 7) {
            STSA(c + 1, nxt);     // LDG latency covered by co-CTA's mma
            CPB(c + 1, nxt);
            CP_COMMIT();
        }
        // ---- mma over chunk c (buffer cur): A * (Bhi + Blo)
        const uint32_t base = sbase + cur * BUFSZ;
        #pragma unroll
        for (int ks = 0; ks < 2; ++ks) {
            uint32_t ah[2][4];
            #pragma unroll
            for (int i = 0; i < 2; i++)
                LDSM4(ah[i], base + aOff[i] + ks * 32);
            #pragma unroll
            for (int jp = 0; jp < 4; jp++) {
                uint32_t bh4[4], bl4[4];
                LDSM4(bh4, base + bOff[jp] + ks * 32);
                LDSM4(bl4, base + bOff[jp] + (BLO - BHI) + ks * 32);
                MMA16816(acc[0*8+2*jp],   ah[0], bh4[0], bh4[1]);
                MMA16816(acc[0*8+2*jp+1], ah[0], bh4[2], bh4[3]);
                MMA16816(acc[1*8+2*jp],   ah[1], bh4[0], bh4[1]);
                MMA16816(acc[1*8+2*jp+1], ah[1], bh4[2], bh4[3]);
                MMA16816(acc[0*8+2*jp],   ah[0], bl4[0], bl4[1]);
                MMA16816(acc[0*8+2*jp+1], ah[0], bl4[2], bl4[3]);
                MMA16816(acc[1*8+2*jp],   ah[1], bl4[0], bl4[1]);
                MMA16816(acc[1*8+2*jp+1], ah[1], bl4[2], bl4[3]);
            }
        }
    }

    // ---- epilogue: bias + ELU, fp32 stores (+ BN partials for AMODE 2)
    const int g  = lane >> 2;
    const int tg = lane & 3;
    float cs[16], cq[16];
    if (AMODE == 2) {
        #pragma unroll
        for (int t = 0; t < 16; ++t) { cs[t] = 0.f; cq[t] = 0.f; }
    }
    #pragma unroll
    for (int i = 0; i < 2; i++) {
        #pragma unroll
        for (int j = 0; j < 8; j++) {
            int colg = nbase + n0w + j*8 + tg*2;
            float b0v = 0.f, b1v = 0.f;
            if (bias) { b0v = __ldg(bias + colg); b1v = __ldg(bias + colg + 1); }
            float* q = acc[i*8+j];
            int rlo = row0 + m0w + i*16 + g;
            int rhi = rlo + 8;
            float2 o0, o1;
            o0.x = q[0] + b0v; o0.y = q[1] + b1v;
            o1.x = q[2] + b0v; o1.y = q[3] + b1v;
            if (do_elu) {
                o0.x = elu_f(o0.x); o0.y = elu_f(o0.y);
                o1.x = elu_f(o1.x); o1.y = elu_f(o1.y);
            }
            if (AMODE == 2) {
                cs[j*2+0] += o0.x + o1.x;
                cs[j*2+1] += o0.y + o1.y;
                cq[j*2+0] += o0.x*o0.x + o1.x*o1.x;
                cq[j*2+1] += o0.y*o0.y + o1.y*o1.y;
            }
            *(float2*)(C + (size_t)rlo * 256 + colg) = o0;
            *(float2*)(C + (size_t)rhi * 256 + colg) = o1;
        }
    }

    if (AMODE == 2) {
        #pragma unroll
        for (int t = 0; t < 16; ++t) {
            #pragma unroll
            for (int o = 4; o <= 16; o <<= 1) {
                cs[t] += __shfl_xor_sync(0xffffffffu, cs[t], o);
                cq[t] += __shfl_xor_sync(0xffffffffu, cq[t], o);
            }
        }
        __syncthreads();
        float* sps = (float*)sm;         // [8 warps][64 cols][2]
        if (lane < 4) {
            #pragma unroll
            for (int j = 0; j < 8; ++j) {
                #pragma unroll
                for (int par = 0; par < 2; ++par) {
                    int col = j*8 + lane*2 + par;
                    sps[(w*64 + col)*2 + 0] = cs[j*2+par];
                    sps[(w*64 + col)*2 + 1] = cq[j*2+par];
                }
            }
        }
        __syncthreads();
        int strip = tid >> 7, col = (tid >> 1) & 63, stat = tid & 1;
        float a2 = 0.f;
        #pragma unroll
        for (int wi = 0; wi < 4; ++wi)
            a2 += sps[((strip*4 + wi)*64 + col)*2 + stat];
        int ch = nbase + strip*64 + col;
        g_p3[((size_t)blockIdx.x * 256 + ch)*2 + stat] = a2;
    }
    #undef STSA
    #undef CPB
}

// ---------------- small node-level SIMT GEMM (M=3200) -----------------------
__global__ __launch_bounds__(256)
void gemm_node(const float* __restrict__ A, int lda, int K,
               const float* __restrict__ W, const float* __restrict__ bias,
               int do_elu, float* __restrict__ C)
{
    __shared__ float sA[16][65];
    __shared__ float sB[16][64];
    const int row0 = blockIdx.x * 64;
    const int col0 = blockIdx.y * 64;
    const int tid  = threadIdx.x;
    const int ty   = tid >> 4, tx = tid & 15;
    float acc[4][4] = {};
    for (int kt = 0; kt < K; kt += 16) {
        #pragma unroll
        for (int i = 0; i < 4; i++) {
            int idx = tid + i * 256;
            int m = idx >> 4, k = idx & 15;
            int kk = kt + k;
            sA[k][m] = (kk < K) ? A[(size_t)(row0 + m) * lda + kk] : 0.f;
        }
        #pragma unroll
        for (int i = 0; i < 4; i++) {
            int idx = tid + i * 256;
            int k = idx >> 6, n = idx & 63;
            int kk = kt + k;
            sB[k][n] = (kk < K) ? W[(size_t)kk * 256 + col0 + n] : 0.f;
        }
        __syncthreads();
        #pragma unroll
        for (int k = 0; k < 16; k++) {
            float a[4], b[4];
            #pragma unroll
            for (int i = 0; i < 4; i++) a[i] = sA[k][ty*4 + i];
            #pragma unroll
            for (int j = 0; j < 4; j++) b[j] = sB[k][tx*4 + j];
            #pragma unroll
            for (int i = 0; i < 4; i++)
                #pragma unroll
                for (int j = 0; j < 4; j++)
                    acc[i][j] += a[i] * b[j];
        }
        __syncthreads();
    }
    #pragma unroll
    for (int i = 0; i < 4; i++) {
        int m = row0 + ty*4 + i;
        #pragma unroll
        for (int j = 0; j < 4; j++) {
            int n = col0 + tx*4 + j;
            float v = acc[i][j];
            if (bias) v += bias[n];
            if (do_elu) v = elu_f(v);
            C[(size_t)m * 256 + n] = v;
        }
    }
}

// ---------------- merged dual node GEMM: same A, two weight mats ------------
__global__ __launch_bounds__(256)
void gemm_node2(const float* __restrict__ A,
                const float* __restrict__ Wa, const float* __restrict__ Wb,
                float* __restrict__ Ca, float* __restrict__ Cb)
{
    const float* W = (blockIdx.y < 4) ? Wa : Wb;
    float* C       = (blockIdx.y < 4) ? Ca : Cb;
    const int col0 = (blockIdx.y & 3) * 64;
    __shared__ float sA[16][65];
    __shared__ float sB[16][64];
    const int row0 = blockIdx.x * 64;
    const int tid  = threadIdx.x;
    const int ty   = tid >> 4, tx = tid & 15;
    float acc[4][4] = {};
    for (int kt = 0; kt < 256; kt += 16) {
        #pragma unroll
        for (int i = 0; i < 4; i++) {
            int idx = tid + i * 256;
            int m = idx >> 4, k = idx & 15;
            sA[k][m] = A[(size_t)(row0 + m) * 256 + kt + k];
        }
        #pragma unroll
        for (int i = 0; i < 4; i++) {
            int idx = tid + i * 256;
            int k = idx >> 6, n = idx & 63;
            sB[k][n] = W[(size_t)(kt + k) * 256 + col0 + n];
        }
        __syncthreads();
        #pragma unroll
        for (int k = 0; k < 16; k++) {
            float a[4], b[4];
            #pragma unroll
            for (int i = 0; i < 4; i++) a[i] = sA[k][ty*4 + i];
            #pragma unroll
            for (int j = 0; j < 4; j++) b[j] = sB[k][tx*4 + j];
            #pragma unroll
            for (int i = 0; i < 4; i++)
                #pragma unroll
                for (int j = 0; j < 4; j++)
                    acc[i][j] += a[i] * b[j];
        }
        __syncthreads();
    }
    #pragma unroll
    for (int i = 0; i < 4; i++) {
        int m = row0 + ty*4 + i;
        #pragma unroll
        for (int j = 0; j < 4; j++)
            C[(size_t)m * 256 + col0 + tx*4 + j] = acc[i][j];
    }
}

// ---------------- edge2node: contiguous 99-edge segment mean ----------------
__global__ void edge2node_k(const float* __restrict__ x, float* __restrict__ out) {
    int nodeRow = blockIdx.x;
    int h = threadIdx.x;
    int b = nodeRow / Nn, n = nodeRow - b * Nn;
    const float* base = x + (size_t)(b * Ee + n * 99) * Hh + h;
    float s = 0.f;
    #pragma unroll 3
    for (int r = 0; r < 99; r++) s += base[(size_t)r * Hh];
    out[(size_t)nodeRow * Hh + h] = s * (1.0f / 9900.0f);
}

// ---------------- BN partial reduce: parallel deterministic tree ------------
__global__ void bn_reduce_k() {
    int ch = blockIdx.x, t = threadIdx.x;
    double s = 0.0, q = 0.0;
    for (int bx = t; bx < NCTA; bx += 256) {
        s += (double)g_p3[((size_t)bx * 256 + ch) * 2 + 0];
        q += (double)g_p3[((size_t)bx * 256 + ch) * 2 + 1];
    }
    __shared__ double ss[256], sq[256];
    ss[t] = s; sq[t] = q;
    __syncthreads();
    for (int st = 128; st > 0; st >>= 1) {
        if (t < st) { ss[t] += ss[t + st]; sq[t] += sq[t + st]; }
        __syncthreads();
    }
    if (t == 0) { g_chS[ch] = ss[0]; g_chQ[ch] = sq[0]; }
}

// ---------------- BN finalize + fold into fc --------------------------------
__global__ void bn_fin3(const float* __restrict__ gamma, const float* __restrict__ beta,
                        const float* __restrict__ W, const float* __restrict__ fb) {
    int ch = threadIdx.x;
    double s = g_chS[ch], q = g_chQ[ch];
    double m = s / (double)BE;
    double v = q / (double)BE - m * m;
    float sc = (float)(rsqrt(v + 1e-5) * (double)gamma[ch]);
    float sh = beta[ch] - (float)m * sc;
    float w0 = W[ch*2 + 0], w1 = W[ch*2 + 1];
    g_fcW[ch*2 + 0] = sc * w0;
    g_fcW[ch*2 + 1] = sc * w1;
    __shared__ float r0s[256], r1s[256];
    r0s[ch] = sh * w0;
    r1s[ch] = sh * w1;
    __syncthreads();
    for (int st = 128; st > 0; st >>= 1) {
        if (ch < st) { r0s[ch] += r0s[ch + st]; r1s[ch] += r1s[ch + st]; }
        __syncthreads();
    }
    if (ch == 0) { g_fcB[0] = r0s[0] + fb[0]; g_fcB[1] = r1s[0] + fb[1]; }
}

// ---------------- final fc (folded BN): warp per row ------------------------
__global__ void fc_k(const float* __restrict__ y, float* __restrict__ out) {
    int gwarp = (blockIdx.x * blockDim.x + threadIdx.x) >> 5;
    int lane  = threadIdx.x & 31;
    if (gwarp >= BE) return;
    const float* row = y + (size_t)gwarp * Hh;
    float a0 = 0.f, a1 = 0.f;
    #pragma unroll
    for (int i = lane; i < Hh; i += 32) {
        float v = row[i];
        a0 += v * g_fcW[i*2 + 0];
        a1 += v * g_fcW[i*2 + 1];
    }
    #pragma unroll
    for (int o = 16; o > 0; o >>= 1) {
        a0 += __shfl_down_sync(0xffffffffu, a0, o);
        a1 += __shfl_down_sync(0xffffffffu, a1, o);
    }
    if (lane == 0) {
        out[(size_t)gwarp * 2 + 0] = a0 + g_fcB[0];
        out[(size_t)gwarp * 2 + 1] = a1 + g_fcB[1];
    }
}

// ---------------------------------------------------------------------------
extern "C" void kernel_launch(void* const* d_in, const int* in_sizes, int n_in,
                              void* d_out, int out_size) {
    const float* inputs  = (const float*)d_in[0];
    const float* rel_rec = (const float*)d_in[1];
    const float* rel_snd = (const float*)d_in[2];
    const float* m1W1 = (const float*)d_in[3];  const float* m1b1 = (const float*)d_in[4];
    const float* m1W2 = (const float*)d_in[5];  const float* m1b2 = (const float*)d_in[6];
    const float* m2W1 = (const float*)d_in[7];  const float* m2b1 = (const float*)d_in[8];
    const float* m2W2 = (const float*)d_in[9];  const float* m2b2 = (const float*)d_in[10];
    const float* m3W1 = (const float*)d_in[11]; const float* m3b1 = (const float*)d_in[12];
    const float* m3W2 = (const float*)d_in[13]; const float* m3b2 = (const float*)d_in[14];
    const float* m4W1 = (const float*)d_in[15]; const float* m4b1 = (const float*)d_in[16];
    const float* m4W2 = (const float*)d_in[17]; const float* m4b2 = (const float*)d_in[18];
    const float* gmma = (const float*)d_in[19]; const float* beta = (const float*)d_in[20];
    const float* fcW  = (const float*)d_in[21]; const float* fcb  = (const float*)d_in[22];
    float* out = (float*)d_out;

    float *h1, *na, *nb, *as_, *ar_, *xskip, *pre, *y4;
    __half *wth, *wtl;
    cudaGetSymbolAddress((void**)&h1, g_h1);
    cudaGetSymbolAddress((void**)&na, g_na);
    cudaGetSymbolAddress((void**)&nb, g_nb);
    cudaGetSymbolAddress((void**)&as_, g_as);
    cudaGetSymbolAddress((void**)&ar_, g_ar);
    cudaGetSymbolAddress((void**)&xskip, g_xskip);
    cudaGetSymbolAddress((void**)&pre, g_pre);
    cudaGetSymbolAddress((void**)&y4, g_y4);
    cudaGetSymbolAddress((void**)&wth, g_WtHi);
    cudaGetSymbolAddress((void**)&wtl, g_WtLo);

    const int DSMEM = 2 * BUFSZ;   // 61440
    cudaFuncSetAttribute(gemm_tc<0>, cudaFuncAttributeMaxDynamicSharedMemorySize, DSMEM);
    cudaFuncSetAttribute(gemm_tc<1>, cudaFuncAttributeMaxDynamicSharedMemorySize, DSMEM);
    cudaFuncSetAttribute(gemm_tc<2>, cudaFuncAttributeMaxDynamicSharedMemorySize, DSMEM);

    dim3 gN(BNr / 64, 4);
    dim3 gN2(BNr / 64, 8);
    dim3 gE(NCTA, 2);
    dim3 tb(32, 32);
    dim3 tg(8, 8);

    // edge index tables + weight prep (transpose + fp16 split)
    build_idx_k<<<(Ee + 127) / 128, 128>>>(rel_rec, rel_snd);
    prep_wt_k<<<tg, tb>>>(m2W2,             wth + 0 * 65536, wtl + 0 * 65536);
    prep_wt_k<<<tg, tb>>>(m4W1 + 512 * 256, wth + 1 * 65536, wtl + 1 * 65536);
    prep_wt_k<<<tg, tb>>>(m4W2,             wth + 2 * 65536, wtl + 2 * 65536);

    // mlp1 (node level)
    gemm_node<<<gN, 256>>>(inputs, FIN, FIN, m1W1, m1b1, 1, na);
    gemm_node<<<gN, 256>>>(na, Hh, Hh, m1W2, m1b2, 1, h1);

    // node projections for mlp2 layer1 (send + recv halves, one launch)
    gemm_node2<<<gN2, 256>>>(h1, m2W1, m2W1 + 256*256, as_, ar_);

    // big GEMM #1 (tensor): xskip = ELU(ELU(as[s]+ar[r]+b1) @ W2 + b2)
    gemm_tc<1><<<gE, 256, DSMEM>>>(nullptr, wth + 0 * 65536, wtl + 0 * 65536,
                                   as_, ar_, m2b1, m2b2, 1, xskip);

    // edge2node + mlp3 (node level)
    edge2node_k<<<BNr, 256>>>(xskip, na);
    gemm_node<<<gN, 256>>>(na, Hh, Hh, m3W1, m3b1, 1, nb);
    gemm_node<<<gN, 256>>>(nb, Hh, Hh, m3W2, m3b2, 1, h1);

    // node projections for mlp4 layer1
    gemm_node2<<<gN2, 256>>>(h1, m4W1, m4W1 + 256*256, as_, ar_);

    // big GEMM #2 (tensor): pre = xskip @ W4_1[512:768]
    gemm_tc<0><<<gE, 256, DSMEM>>>(xskip, wth + 1 * 65536, wtl + 1 * 65536,
                                   nullptr, nullptr, nullptr, nullptr, 0, pre);

    // big GEMM #3 (tensor): y4 = ELU(ELU(pre + as[s]+ar[r]+b1) @ W4_2 + b2)
    //                        + fused per-CTA BN partial stats
    gemm_tc<2><<<gE, 256, DSMEM>>>(pre, wth + 2 * 65536, wtl + 2 * 65536,
                                   as_, ar_, m4b1, m4b2, 1, y4);

    // BN reduce (parallel deterministic), finalize, final fc
    bn_reduce_k<<<256, 256>>>();
    bn_fin3<<<1, 256>>>(gmma, beta, fcW, fcb);
    fc_k<<<(BE * 32 + 255) / 256, 256>>>(y4, out);
}